// round 13
// baseline (speedup 1.0000x reference)
#include <cuda_runtime.h>
#include <cuda_fp16.h>
#include <cstdint>
#include <cmath>

// ---------------- problem constants ----------------
#define HID   3072
#define NH    24
#define HD    128
#define MLPD  12288
#define BB    2
#define LL    2048
#define NTOK  (BB*LL)            // 4096
#define N1    (3*HID + MLPD)     // 21504
#define K2    (HID + MLPD)       // 15360
#define MOD3  (3*HID)            // 9216
#define QKV3  (3*HID)            // 9216
#define SPLITK 5
#define KSPL  (K2/SPLITK)        // 3072

// ---------------- scratch (device globals; no runtime allocs) ----------------
__device__ float  g_mod [BB*MOD3];
__device__ __half g_xh  [(size_t)NTOK*HID];
__device__ __half g_h   [(size_t)NTOK*QKV3];   // qkv only
__device__ __half g_a2h [(size_t)NTOK*K2];
__device__ __half g_w1t [(size_t)N1*HID];      // lin1_w^T [N1, HID] fp16
__device__ __half g_w2t [(size_t)HID*K2];      // lin2_w^T [HID, K2] fp16
__device__ __half g_part[(size_t)SPLITK*NTOK*HID]; // split-K partials (fp16)

// ---------------- helpers ----------------
__device__ __forceinline__ void cp_async16(void* sptr, const void* gptr){
    unsigned sa = (unsigned)__cvta_generic_to_shared(sptr);
    asm volatile("cp.async.cg.shared.global [%0], [%1], 16;\n" :: "r"(sa), "l"(gptr));
}
__device__ __forceinline__ void cp_commit(){ asm volatile("cp.async.commit_group;\n"); }
template<int N> __device__ __forceinline__ void cp_wait(){ asm volatile("cp.async.wait_group %0;\n" :: "n"(N)); }

__device__ __forceinline__ float gelu_tanh(float x){
    float x3 = x*x*x;
    return 0.5f*x*(1.0f + tanhf(0.7978845608028654f*(x + 0.044715f*x3)));
}
__device__ __forceinline__ void ldm_x4(unsigned* r, unsigned addr){
    asm volatile("ldmatrix.sync.aligned.m8n8.x4.shared.b16 {%0,%1,%2,%3}, [%4];\n"
        : "=r"(r[0]), "=r"(r[1]), "=r"(r[2]), "=r"(r[3]) : "r"(addr));
}
__device__ __forceinline__ void mma16(float* c, const unsigned* a, const unsigned* b){
    asm volatile("mma.sync.aligned.m16n8k16.row.col.f32.f16.f16.f32 "
        "{%0,%1,%2,%3}, {%4,%5,%6,%7}, {%8,%9}, {%0,%1,%2,%3};\n"
        : "+f"(c[0]), "+f"(c[1]), "+f"(c[2]), "+f"(c[3])
        : "r"(a[0]), "r"(a[1]), "r"(a[2]), "r"(a[3]), "r"(b[0]), "r"(b[1]));
}

// ---------------- kernel 0: transpose + fp16-round weights (64x64, vectorized) ----------------
__global__ void __launch_bounds__(256, 4)
transpose_half(const float* __restrict__ in, __half* __restrict__ out,
               int K, int N){
    __shared__ float tile[64][65];
    int n0 = blockIdx.x*64, k0 = blockIdx.y*64;
    int tx = threadIdx.x & 15;
    int ty = threadIdx.x >> 4;
    #pragma unroll
    for (int p = 0; p < 4; p++){
        int k = ty + p*16;
        float4 v = *(const float4*)&in[(size_t)(k0+k)*N + n0 + tx*4];
        tile[k][tx*4+0] = v.x;
        tile[k][tx*4+1] = v.y;
        tile[k][tx*4+2] = v.z;
        tile[k][tx*4+3] = v.w;
    }
    __syncthreads();
    int cx = threadIdx.x & 7;
    int cy = threadIdx.x >> 3;
    #pragma unroll
    for (int p = 0; p < 2; p++){
        int n = cy + p*32;
        __half hbuf[8];
        #pragma unroll
        for (int i = 0; i < 8; i++)
            hbuf[i] = __float2half_rn(tile[cx*8+i][n]);
        *(uint4*)&out[(size_t)(n0+n)*K + k0 + cx*8] = *(uint4*)hbuf;
    }
}

// ---------------- kernel 1: mod = silu(vec) @ mod_w + mod_b ----------------
__global__ void mod_kernel(const float* __restrict__ vec,
                           const float* __restrict__ W,
                           const float* __restrict__ bias,
                           float* __restrict__ mod){
    __shared__ float sv[HID];
    int b = blockIdx.y;
    for (int i = threadIdx.x; i < HID; i += 128){
        float v = vec[b*HID + i];
        sv[i] = v / (1.0f + expf(-v));
    }
    __syncthreads();
    int j = blockIdx.x*128 + threadIdx.x;
    const float* w = W + j;
    float a0 = 0.f, a1 = 0.f, a2 = 0.f, a3 = 0.f;
    #pragma unroll 4
    for (int k = 0; k < HID; k += 4){
        a0 += sv[k  ] * w[(size_t)(k  )*MOD3];
        a1 += sv[k+1] * w[(size_t)(k+1)*MOD3];
        a2 += sv[k+2] * w[(size_t)(k+2)*MOD3];
        a3 += sv[k+3] * w[(size_t)(k+3)*MOD3];
    }
    mod[b*MOD3 + j] = bias[j] + ((a0+a1)+(a2+a3));
}

// ---------------- kernel 2: x_mod = (1+scale)*LN(x) + shift  -> fp16 ----------------
__global__ void ln_mod_kernel(const float* __restrict__ x,
                              const float* __restrict__ mod,
                              __half* __restrict__ xh){
    int t = blockIdx.x;
    int b = t >> 11;
    const float4* xr = (const float4*)(x + (size_t)t*HID);
    float4 v[3];
    float s = 0.f, s2 = 0.f;
    #pragma unroll
    for (int i = 0; i < 3; i++){
        v[i] = xr[threadIdx.x + i*256];
        s  += v[i].x + v[i].y + v[i].z + v[i].w;
        s2 += v[i].x*v[i].x + v[i].y*v[i].y + v[i].z*v[i].z + v[i].w*v[i].w;
    }
    int lane = threadIdx.x & 31, w = threadIdx.x >> 5;
    #pragma unroll
    for (int o = 16; o > 0; o >>= 1){
        s  += __shfl_xor_sync(0xffffffffu, s,  o);
        s2 += __shfl_xor_sync(0xffffffffu, s2, o);
    }
    __shared__ float red[64];
    if (lane == 0){ red[w] = s; red[32+w] = s2; }
    __syncthreads();
    float ts = 0.f, ts2 = 0.f;
    #pragma unroll
    for (int i = 0; i < 8; i++){ ts += red[i]; ts2 += red[32+i]; }
    float mu  = ts  * (1.0f/HID);
    float var = ts2 * (1.0f/HID) - mu*mu;
    float rr  = rsqrtf(var + 1e-6f);

    const float* shiftp = mod + b*MOD3;
    const float* scalep = shiftp + HID;
    uint2* dst = (uint2*)(xh + (size_t)t*HID);
    #pragma unroll
    for (int i = 0; i < 3; i++){
        int j = threadIdx.x + i*256;
        float4 sh = ((const float4*)shiftp)[j];
        float4 sc = ((const float4*)scalep)[j];
        float ox = (1.f+sc.x)*((v[i].x-mu)*rr) + sh.x;
        float oy = (1.f+sc.y)*((v[i].y-mu)*rr) + sh.y;
        float oz = (1.f+sc.z)*((v[i].z-mu)*rr) + sh.z;
        float ow = (1.f+sc.w)*((v[i].w-mu)*rr) + sh.w;
        __half2 p0 = __floats2half2_rn(ox, oy);
        __half2 p1 = __floats2half2_rn(oz, ow);
        uint2 u; u.x = *(unsigned*)&p0; u.y = *(unsigned*)&p1;
        dst[j] = u;
    }
}

// ---------------- fp16 mma.sync GEMM (128x128 tile, 4 warps, 2 CTAs/SM) ----------------
#define BM 128
#define BN 128
#define BK 64
#define GSTAGES 3
#define SAB (BM*128)             // 16384 B
#define SBB (BN*128)             // 16384 B
#define STB (SAB+SBB)            // 32768 B
#define GEMM_SMEM (GSTAGES*STB)  // 98304 B
#define GROUP_M 32               // single m-group: B weights stream from DRAM once
#define LDC_S 136                // smem C-tile row stride in halves (conflict-free)

template<int EPI>
__global__ void __launch_bounds__(128, 2)
gemm_f16(const __half* __restrict__ A, int lda,
         const __half* __restrict__ Bt, int ldb,
         const float* __restrict__ bias,
         void* __restrict__ Cv,
         int M, int N, int K,
         void* __restrict__ Cv2){
    extern __shared__ char smem[];
    const unsigned smem_u = (unsigned)__cvta_generic_to_shared(smem);
    const int tid  = threadIdx.x;
    const int lane = tid & 31;
    const int wid  = tid >> 5;
    const int m_off = (wid & 1)*64;
    const int n_off = (wid >> 1)*64;

    int npm = M/BM, npn = N/BN;
    int tiles = npm*npn;
    int bx = blockIdx.x;
    int sk = 0;
    if constexpr (EPI == 2){ sk = bx / tiles; bx = bx % tiles; }

    int pig = GROUP_M*npn;
    int gidg = bx / pig;
    int first = gidg*GROUP_M;
    int gsz = (npm - first < GROUP_M) ? (npm - first) : GROUP_M;
    int inGroup = bx % pig;
    int pm = first + (inGroup % gsz);
    int pn = inGroup / gsz;

    const __half* Ablk = A  + (size_t)(pm*BM)*lda + (EPI==2 ? sk*KSPL : 0);
    const __half* Bblk = Bt + (size_t)(pn*BN)*ldb + (EPI==2 ? sk*KSPL : 0);

    float acc[4][8][4];
    #pragma unroll
    for (int a = 0; a < 4; a++)
        #pragma unroll
        for (int b = 0; b < 8; b++)
            #pragma unroll
            for (int c = 0; c < 4; c++) acc[a][b][c] = 0.f;

    const int KT = K/BK;

    auto load_slab = [&](int slot, int kt){
        char* sA = smem + slot*STB;
        char* sB = sA + SAB;
        const __half* Ag = Ablk + kt*BK;
        #pragma unroll
        for (int i = 0; i < 8; i++){
            int idx = i*128 + tid;
            int r = idx >> 3, c = idx & 7;
            cp_async16(sA + r*128 + ((c ^ (r & 7))<<4), Ag + (size_t)r*lda + c*8);
        }
        const __half* Bg = Bblk + kt*BK;
        #pragma unroll
        for (int i = 0; i < 8; i++){
            int idx = i*128 + tid;
            int r = idx >> 3, c = idx & 7;
            cp_async16(sB + r*128 + ((c ^ (r & 7))<<4), Bg + (size_t)r*ldb + c*8);
        }
    };

    load_slab(0, 0); cp_commit();
    if (KT > 1) load_slab(1, 1);
    cp_commit();

    const int g  = lane >> 3;
    const int li = lane & 7;

    // register double-buffered fragments
    unsigned af[2][4][4], bq[2][4][4];

    auto load_frags = [&](unsigned sA_u, unsigned sB_u, int ks, int buf){
        #pragma unroll
        for (int mt = 0; mt < 4; mt++){
            int row = m_off + mt*16 + li + (g & 1)*8;
            int ch  = ks*2 + (g >> 1);
            ldm_x4(af[buf][mt], sA_u + row*128 + ((ch ^ (row & 7))<<4));
        }
        #pragma unroll
        for (int np = 0; np < 4; np++){
            int row = n_off + np*16 + li + (g >> 1)*8;
            int ch  = ks*2 + (g & 1);
            ldm_x4(bq[buf][np], sB_u + row*128 + ((ch ^ (row & 7))<<4));
        }
    };

    for (int kt = 0; kt < KT; kt++){
        cp_wait<1>();
        __syncthreads();
        int kf = kt + 2;
        if (kf < KT) load_slab(kf % GSTAGES, kf);
        cp_commit();

        const unsigned sA_u = smem_u + (kt % GSTAGES)*STB;
        const unsigned sB_u = sA_u + SAB;

        load_frags(sA_u, sB_u, 0, 0);
        #pragma unroll
        for (int ks = 0; ks < 4; ks++){
            const int cur = ks & 1;
            if (ks < 3) load_frags(sA_u, sB_u, ks + 1, cur ^ 1);
            #pragma unroll
            for (int mt = 0; mt < 4; mt++)
                #pragma unroll
                for (int np = 0; np < 4; np++){
                    mma16(acc[mt][np*2+0], af[cur][mt], &bq[cur][np][0]);
                    mma16(acc[mt][np*2+1], af[cur][mt], &bq[cur][np][2]);
                }
        }
    }

    // ---- epilogue: stage C tile in smem, then coalesced uint4 stores ----
    cp_wait<0>();
    __syncthreads();                 // pipeline smem now free for reuse
    __half* ctile = (__half*)smem;   // [BM][LDC_S]
    const int lr = lane >> 2, lc = lane & 3;

    #pragma unroll
    for (int mt = 0; mt < 4; mt++){
        #pragma unroll
        for (int nt = 0; nt < 8; nt++){
            int cl = n_off + nt*8 + lc*2;        // local col
            int cg = pn*BN + cl;                 // global col
            #pragma unroll
            for (int half_ = 0; half_ < 2; half_++){
                int rl = m_off + mt*16 + lr + half_*8;   // local row
                float v0 = acc[mt][nt][half_*2+0];
                float v1 = acc[mt][nt][half_*2+1];
                __half2 hv;
                if constexpr (EPI == 1){
                    v0 += bias[cg]; v1 += bias[cg+1];
                    if (pn >= QKV3/BN)
                        hv = __floats2half2_rn(gelu_tanh(v0), gelu_tanh(v1));
                    else
                        hv = __floats2half2_rn(v0, v1);
                } else {
                    hv = __floats2half2_rn(v0, v1);
                }
                *(__half2*)&ctile[rl*LDC_S + cl] = hv;
            }
        }
    }
    __syncthreads();

    // cooperative coalesced write: 128 rows x 128 halves (16 uint4 per row)
    __half* dstbase;
    size_t stride;
    if constexpr (EPI == 1){
        if (pn >= QKV3/BN){ dstbase = (__half*)Cv2 + HID + (pn*BN - QKV3); stride = K2; }
        else              { dstbase = (__half*)Cv  + pn*BN;               stride = QKV3; }
    } else {
        dstbase = (__half*)Cv + (size_t)sk*NTOK*HID + pn*BN;
        stride = HID;
    }
    const int row0 = pm*BM;
    #pragma unroll
    for (int j = 0; j < 16; j++){
        int idx = j*128 + tid;       // 0..2047
        int rl = idx >> 4;           // row 0..127
        int q  = idx & 15;           // uint4 index within row
        *(uint4*)&dstbase[(size_t)(row0+rl)*stride + q*8] =
            *(const uint4*)&ctile[rl*LDC_S + q*8];
    }
}

// ---------------- kernel: split-K reduce + bias + residual + gate ----------------
__global__ void __launch_bounds__(256, 4)
reduce_out(const __half* __restrict__ part,
           const float* __restrict__ x,
           const float* __restrict__ bias,
           const float* __restrict__ mod,
           float* __restrict__ out){
    size_t idx = (size_t)blockIdx.x*256 + threadIdx.x;
    int r = (int)(idx / (HID/4));
    int c = (int)(idx % (HID/4)) * 4;
    const float* gate = mod + (r >> 11)*MOD3 + 2*HID;
    float s0, s1, s2, s3;
    {
        float4 bv = *(const float4*)&bias[c];
        s0 = bv.x; s1 = bv.y; s2 = bv.z; s3 = bv.w;
    }
    #pragma unroll
    for (int p = 0; p < SPLITK; p++){
        uint2 u = *(const uint2*)&part[(size_t)p*NTOK*HID + (size_t)r*HID + c];
        __half2 h0 = *(__half2*)&u.x, h1 = *(__half2*)&u.y;
        float2 f0 = __half22float2(h0), f1 = __half22float2(h1);
        s0 += f0.x; s1 += f0.y; s2 += f1.x; s3 += f1.y;
    }
    float4 g4 = *(const float4*)&gate[c];
    float4 xv = *(const float4*)&x[(size_t)r*HID + c];
    float4 o;
    o.x = xv.x + g4.x*s0;
    o.y = xv.y + g4.y*s1;
    o.z = xv.z + g4.z*s2;
    o.w = xv.w + g4.w*s3;
    *(float4*)&out[(size_t)r*HID + c] = o;
}

// ---------------- kernel 4: per-token head-attention -> A2[:, :3072] ----------------
__global__ void __launch_bounds__(256, 4)
attn_kernel(const __half* __restrict__ h,
            const float* __restrict__ pe,
            const float* __restrict__ qsc,
            const float* __restrict__ ksc,
            __half* __restrict__ a2){
    __shared__ float sq[NH*HD], sk[NH*HD], sv[NH*HD], ss[NH*NH];
    const int t = blockIdx.x;
    const int b = t >> 11;
    const int l = t & 2047;
    const int tid = threadIdx.x;
    const int lane = tid & 31;
    const int w = tid >> 5;

    const __half* hrow = h + (size_t)t*QKV3;

    for (int j = tid; j < 2304; j += 256){
        uint2 u = ((const uint2*)hrow)[j];
        __half2 p0 = *(__half2*)&u.x, p1 = *(__half2*)&u.y;
        float2 f0 = __half22float2(p0), f1 = __half22float2(p1);
        float4 v4; v4.x = f0.x; v4.y = f0.y; v4.z = f1.x; v4.w = f1.y;
        float* dst = (j < 768) ? sq : (j < 1536 ? sk : sv);
        int o = (j < 768) ? j : (j < 1536 ? j - 768 : j - 1536);
        ((float4*)dst)[o] = v4;
    }
    __syncthreads();

    const float* pet = pe + ((size_t)(b*LL + l))*(HD/2)*4;
    float4 qs4 = *(const float4*)&qsc[lane*4];
    float4 ks4 = *(const float4*)&ksc[lane*4];
    float4 e0 = *(const float4*)&pet[lane*8];
    float4 e1 = *(const float4*)&pet[lane*8 + 4];

    #pragma unroll
    for (int i = 0; i < 3; i++){
        int hh = w + 8*i;
        float4 q4 = *(float4*)&sq[hh*HD + lane*4];
        float4 k4 = *(float4*)&sk[hh*HD + lane*4];
        float pq = q4.x*q4.x + q4.y*q4.y + q4.z*q4.z + q4.w*q4.w;
        float pk = k4.x*k4.x + k4.y*k4.y + k4.z*k4.z + k4.w*k4.w;
        #pragma unroll
        for (int o = 16; o > 0; o >>= 1){
            pq += __shfl_xor_sync(0xffffffffu, pq, o);
            pk += __shfl_xor_sync(0xffffffffu, pk, o);
        }
        float rq = rsqrtf(pq*(1.0f/HD) + 1e-6f);
        float rk = rsqrtf(pk*(1.0f/HD) + 1e-6f);
        q4.x *= rq*qs4.x; q4.y *= rq*qs4.y; q4.z *= rq*qs4.z; q4.w *= rq*qs4.w;
        k4.x *= rk*ks4.x; k4.y *= rk*ks4.y; k4.z *= rk*ks4.z; k4.w *= rk*ks4.w;
        float4 qo, ko;
        qo.x = e0.x*q4.x + e0.y*q4.y;  qo.y = e0.z*q4.x + e0.w*q4.y;
        qo.z = e1.x*q4.z + e1.y*q4.w;  qo.w = e1.z*q4.z + e1.w*q4.w;
        ko.x = e0.x*k4.x + e0.y*k4.y;  ko.y = e0.z*k4.x + e0.w*k4.y;
        ko.z = e1.x*k4.z + e1.y*k4.w;  ko.w = e1.z*k4.z + e1.w*k4.w;
        const float sc = 0.08838834764831845f; // 1/sqrt(128)
        qo.x *= sc; qo.y *= sc; qo.z *= sc; qo.w *= sc;
        *(float4*)&sq[hh*HD + lane*4] = qo;
        *(float4*)&sk[hh*HD + lane*4] = ko;
    }
    __syncthreads();

    #pragma unroll
    for (int i = 0; i < 3; i++){
        int hh = w + 8*i;
        float4 qq = *(const float4*)&sq[hh*HD + lane*4];
        for (int gg = 0; gg < NH; gg++){
            float4 kk = *(const float4*)&sk[gg*HD + lane*4];
            float d = qq.x*kk.x + qq.y*kk.y + qq.z*kk.z + qq.w*kk.w;
            #pragma unroll
            for (int o = 16; o > 0; o >>= 1) d += __shfl_xor_sync(0xffffffffu, d, o);
            if (lane == 0) ss[hh*NH + gg] = d;
        }
    }
    __syncwarp();

    #pragma unroll
    for (int i = 0; i < 3; i++){
        int hh = w + 8*i;
        float v = (lane < NH) ? ss[hh*NH + lane] : -1e30f;
        float mx = v;
        #pragma unroll
        for (int o = 16; o > 0; o >>= 1) mx = fmaxf(mx, __shfl_xor_sync(0xffffffffu, mx, o));
        float e = (lane < NH) ? expf(v - mx) : 0.f;
        float sum = e;
        #pragma unroll
        for (int o = 16; o > 0; o >>= 1) sum += __shfl_xor_sync(0xffffffffu, sum, o);
        if (lane < NH) ss[hh*NH + lane] = e / sum;
    }
    __syncwarp();

    #pragma unroll
    for (int i = 0; i < 3; i++){
        int hh = w + 8*i;
        float4 accv; accv.x = accv.y = accv.z = accv.w = 0.f;
        for (int gg = 0; gg < NH; gg++){
            float p = ss[hh*NH + gg];
            float4 vv = *(const float4*)&sv[gg*HD + lane*4];
            accv.x += p*vv.x; accv.y += p*vv.y; accv.z += p*vv.z; accv.w += p*vv.w;
        }
        __half2 p0 = __floats2half2_rn(accv.x, accv.y);
        __half2 p1 = __floats2half2_rn(accv.z, accv.w);
        uint2 u; u.x = *(unsigned*)&p0; u.y = *(unsigned*)&p1;
        *(uint2*)&a2[(size_t)t*K2 + hh*HD + lane*4] = u;
    }
}

// ---------------- launch ----------------
extern "C" void kernel_launch(void* const* d_in, const int* in_sizes, int n_in,
                              void* d_out, int out_size){
    const float* x      = (const float*)d_in[0];
    const float* vec    = (const float*)d_in[1];
    const float* pe     = (const float*)d_in[2];
    const float* mod_w  = (const float*)d_in[3];
    const float* mod_b  = (const float*)d_in[4];
    const float* lin1_w = (const float*)d_in[5];
    const float* lin1_b = (const float*)d_in[6];
    const float* lin2_w = (const float*)d_in[7];
    const float* lin2_b = (const float*)d_in[8];
    const float* q_scale= (const float*)d_in[9];
    const float* k_scale= (const float*)d_in[10];
    float* out = (float*)d_out;

    float *d_mod;
    __half *d_xh, *d_h, *d_a2h, *d_w1t, *d_w2t, *d_part;
    cudaGetSymbolAddress((void**)&d_mod,  g_mod);
    cudaGetSymbolAddress((void**)&d_xh,   g_xh);
    cudaGetSymbolAddress((void**)&d_h,    g_h);
    cudaGetSymbolAddress((void**)&d_a2h,  g_a2h);
    cudaGetSymbolAddress((void**)&d_w1t,  g_w1t);
    cudaGetSymbolAddress((void**)&d_w2t,  g_w2t);
    cudaGetSymbolAddress((void**)&d_part, g_part);

    cudaFuncSetAttribute(gemm_f16<1>, cudaFuncAttributeMaxDynamicSharedMemorySize, GEMM_SMEM);
    cudaFuncSetAttribute(gemm_f16<2>, cudaFuncAttributeMaxDynamicSharedMemorySize, GEMM_SMEM);

    // 0) transpose + fp16-round weights
    transpose_half<<<dim3(N1/64, HID/64), 256>>>(lin1_w, d_w1t, HID, N1);
    transpose_half<<<dim3(HID/64, K2/64), 256>>>(lin2_w, d_w2t, K2, HID);

    // 1) mod = silu(vec) @ mod_w + mod_b
    mod_kernel<<<dim3(MOD3/128, BB), 128>>>(vec, mod_w, mod_b, d_mod);

    // 2) x_mod = (1 + scale) * LN(x) + shift  (fp16 out)
    ln_mod_kernel<<<NTOK, 256>>>(x, d_mod, d_xh);

    // 3) h = x_mod @ lin1_w + lin1_b ; qkv -> g_h, gelu(mlp) -> g_a2h
    gemm_f16<1><<<(NTOK/BM)*(N1/BN), 128, GEMM_SMEM>>>(
        d_xh, HID, d_w1t, HID, lin1_b, d_h, NTOK, N1, HID, d_a2h);

    // 4) per-token attention -> A2[:, :3072]
    attn_kernel<<<NTOK, 256>>>(d_h, pe, q_scale, k_scale, d_a2h);

    // 5a) split-K partials: A2 @ lin2_w  (SPLITK=5 → 3840 CTAs ≈ 12.97 waves @ 296 conc.)
    gemm_f16<2><<<(NTOK/BM)*(HID/BN)*SPLITK, 128, GEMM_SMEM>>>(
        d_a2h, K2, d_w2t, K2, nullptr, d_part, NTOK, HID, KSPL, nullptr);

    // 5b) out = x + gate*(sum partials + bias)
    reduce_out<<<(NTOK*HID/4)/256, 256>>>(d_part, x, lin2_b, d_mod, out);
}

// round 14
// speedup vs baseline: 1.0053x; 1.0053x over previous
#include <cuda_runtime.h>
#include <cuda_fp16.h>
#include <cstdint>
#include <cmath>

// ---------------- problem constants ----------------
#define HID   3072
#define NH    24
#define HD    128
#define MLPD  12288
#define BB    2
#define LL    2048
#define NTOK  (BB*LL)            // 4096
#define N1    (3*HID + MLPD)     // 21504
#define K2    (HID + MLPD)       // 15360
#define MOD3  (3*HID)            // 9216
#define QKV3  (3*HID)            // 9216
#define SPLITK 5
#define KSPL  (K2/SPLITK)        // 3072

// ---------------- scratch (device globals; no runtime allocs) ----------------
__device__ float  g_mod [BB*MOD3];
__device__ __half g_xh  [(size_t)NTOK*HID];
__device__ __half g_h   [(size_t)NTOK*QKV3];   // qkv only
__device__ __half g_a2h [(size_t)NTOK*K2];
__device__ __half g_w1t [(size_t)N1*HID];      // lin1_w^T [N1, HID] fp16
__device__ __half g_w2t [(size_t)HID*K2];      // lin2_w^T [HID, K2] fp16
__device__ __half g_part[(size_t)SPLITK*NTOK*HID]; // split-K partials (fp16)

// ---------------- helpers ----------------
__device__ __forceinline__ void cp_async16(void* sptr, const void* gptr){
    unsigned sa = (unsigned)__cvta_generic_to_shared(sptr);
    asm volatile("cp.async.cg.shared.global [%0], [%1], 16;\n" :: "r"(sa), "l"(gptr));
}
__device__ __forceinline__ void cp_commit(){ asm volatile("cp.async.commit_group;\n"); }
template<int N> __device__ __forceinline__ void cp_wait(){ asm volatile("cp.async.wait_group %0;\n" :: "n"(N)); }

__device__ __forceinline__ float gelu_tanh(float x){
    float x3 = x*x*x;
    return 0.5f*x*(1.0f + tanhf(0.7978845608028654f*(x + 0.044715f*x3)));
}
__device__ __forceinline__ void ldm_x4(unsigned* r, unsigned addr){
    asm volatile("ldmatrix.sync.aligned.m8n8.x4.shared.b16 {%0,%1,%2,%3}, [%4];\n"
        : "=r"(r[0]), "=r"(r[1]), "=r"(r[2]), "=r"(r[3]) : "r"(addr));
}
__device__ __forceinline__ void mma16(float* c, const unsigned* a, const unsigned* b){
    asm volatile("mma.sync.aligned.m16n8k16.row.col.f32.f16.f16.f32 "
        "{%0,%1,%2,%3}, {%4,%5,%6,%7}, {%8,%9}, {%0,%1,%2,%3};\n"
        : "+f"(c[0]), "+f"(c[1]), "+f"(c[2]), "+f"(c[3])
        : "r"(a[0]), "r"(a[1]), "r"(a[2]), "r"(a[3]), "r"(b[0]), "r"(b[1]));
}

// ---------------- kernel 0: transpose + fp16-round weights (64x64, vectorized) ----------------
__global__ void __launch_bounds__(256, 4)
transpose_half(const float* __restrict__ in, __half* __restrict__ out,
               int K, int N){
    __shared__ float tile[64][65];
    int n0 = blockIdx.x*64, k0 = blockIdx.y*64;
    int tx = threadIdx.x & 15;
    int ty = threadIdx.x >> 4;
    #pragma unroll
    for (int p = 0; p < 4; p++){
        int k = ty + p*16;
        float4 v = *(const float4*)&in[(size_t)(k0+k)*N + n0 + tx*4];
        tile[k][tx*4+0] = v.x;
        tile[k][tx*4+1] = v.y;
        tile[k][tx*4+2] = v.z;
        tile[k][tx*4+3] = v.w;
    }
    __syncthreads();
    int cx = threadIdx.x & 7;
    int cy = threadIdx.x >> 3;
    #pragma unroll
    for (int p = 0; p < 2; p++){
        int n = cy + p*32;
        __half hbuf[8];
        #pragma unroll
        for (int i = 0; i < 8; i++)
            hbuf[i] = __float2half_rn(tile[cx*8+i][n]);
        *(uint4*)&out[(size_t)(n0+n)*K + k0 + cx*8] = *(uint4*)hbuf;
    }
}

// ---------------- kernel 1: mod = silu(vec) @ mod_w + mod_b ----------------
__global__ void mod_kernel(const float* __restrict__ vec,
                           const float* __restrict__ W,
                           const float* __restrict__ bias,
                           float* __restrict__ mod){
    __shared__ float sv[HID];
    int b = blockIdx.y;
    for (int i = threadIdx.x; i < HID; i += 128){
        float v = vec[b*HID + i];
        sv[i] = v / (1.0f + expf(-v));
    }
    __syncthreads();
    int j = blockIdx.x*128 + threadIdx.x;
    const float* w = W + j;
    float a0 = 0.f, a1 = 0.f, a2 = 0.f, a3 = 0.f;
    #pragma unroll 4
    for (int k = 0; k < HID; k += 4){
        a0 += sv[k  ] * w[(size_t)(k  )*MOD3];
        a1 += sv[k+1] * w[(size_t)(k+1)*MOD3];
        a2 += sv[k+2] * w[(size_t)(k+2)*MOD3];
        a3 += sv[k+3] * w[(size_t)(k+3)*MOD3];
    }
    mod[b*MOD3 + j] = bias[j] + ((a0+a1)+(a2+a3));
}

// ---------------- kernel 2: x_mod = (1+scale)*LN(x) + shift  -> fp16 ----------------
__global__ void ln_mod_kernel(const float* __restrict__ x,
                              const float* __restrict__ mod,
                              __half* __restrict__ xh){
    int t = blockIdx.x;
    int b = t >> 11;
    const float4* xr = (const float4*)(x + (size_t)t*HID);
    float4 v[3];
    float s = 0.f, s2 = 0.f;
    #pragma unroll
    for (int i = 0; i < 3; i++){
        v[i] = xr[threadIdx.x + i*256];
        s  += v[i].x + v[i].y + v[i].z + v[i].w;
        s2 += v[i].x*v[i].x + v[i].y*v[i].y + v[i].z*v[i].z + v[i].w*v[i].w;
    }
    int lane = threadIdx.x & 31, w = threadIdx.x >> 5;
    #pragma unroll
    for (int o = 16; o > 0; o >>= 1){
        s  += __shfl_xor_sync(0xffffffffu, s,  o);
        s2 += __shfl_xor_sync(0xffffffffu, s2, o);
    }
    __shared__ float red[64];
    if (lane == 0){ red[w] = s; red[32+w] = s2; }
    __syncthreads();
    float ts = 0.f, ts2 = 0.f;
    #pragma unroll
    for (int i = 0; i < 8; i++){ ts += red[i]; ts2 += red[32+i]; }
    float mu  = ts  * (1.0f/HID);
    float var = ts2 * (1.0f/HID) - mu*mu;
    float rr  = rsqrtf(var + 1e-6f);

    const float* shiftp = mod + b*MOD3;
    const float* scalep = shiftp + HID;
    uint2* dst = (uint2*)(xh + (size_t)t*HID);
    #pragma unroll
    for (int i = 0; i < 3; i++){
        int j = threadIdx.x + i*256;
        float4 sh = ((const float4*)shiftp)[j];
        float4 sc = ((const float4*)scalep)[j];
        float ox = (1.f+sc.x)*((v[i].x-mu)*rr) + sh.x;
        float oy = (1.f+sc.y)*((v[i].y-mu)*rr) + sh.y;
        float oz = (1.f+sc.z)*((v[i].z-mu)*rr) + sh.z;
        float ow = (1.f+sc.w)*((v[i].w-mu)*rr) + sh.w;
        __half2 p0 = __floats2half2_rn(ox, oy);
        __half2 p1 = __floats2half2_rn(oz, ow);
        uint2 u; u.x = *(unsigned*)&p0; u.y = *(unsigned*)&p1;
        dst[j] = u;
    }
}

// ---------------- fp16 mma.sync GEMM (128x128 tile, 4 warps, 2 CTAs/SM) ----------------
#define BM 128
#define BN 128
#define BK 64
#define GSTAGES 3
#define SAB (BM*128)             // 16384 B
#define SBB (BN*128)             // 16384 B
#define STB (SAB+SBB)            // 32768 B
#define GEMM_SMEM (GSTAGES*STB)  // 98304 B
#define GROUP_M 32
#define LDC_S 136                // smem C-tile row stride in halves (conflict-free)

template<int EPI>
__global__ void __launch_bounds__(128, 2)
gemm_f16(const __half* __restrict__ A, int lda,
         const __half* __restrict__ Bt, int ldb,
         const float* __restrict__ bias,
         void* __restrict__ Cv,
         int M, int N, int K,
         void* __restrict__ Cv2){
    extern __shared__ char smem[];
    const unsigned smem_u = (unsigned)__cvta_generic_to_shared(smem);
    const int tid  = threadIdx.x;
    const int lane = tid & 31;
    const int wid  = tid >> 5;
    const int m_off = (wid & 1)*64;
    const int n_off = (wid >> 1)*64;

    int npm = M/BM, npn = N/BN;
    int tiles = npm*npn;
    int bx = blockIdx.x;
    int sk = 0;
    if constexpr (EPI == 2){ sk = bx / tiles; bx = bx % tiles; }

    int pig = GROUP_M*npn;
    int gidg = bx / pig;
    int first = gidg*GROUP_M;
    int gsz = (npm - first < GROUP_M) ? (npm - first) : GROUP_M;
    int inGroup = bx % pig;
    int pm = first + (inGroup % gsz);
    int pn = inGroup / gsz;

    const __half* Ablk = A  + (size_t)(pm*BM)*lda + (EPI==2 ? sk*KSPL : 0);
    const __half* Bblk = Bt + (size_t)(pn*BN)*ldb + (EPI==2 ? sk*KSPL : 0);

    float acc[4][8][4];
    #pragma unroll
    for (int a = 0; a < 4; a++)
        #pragma unroll
        for (int b = 0; b < 8; b++)
            #pragma unroll
            for (int c = 0; c < 4; c++) acc[a][b][c] = 0.f;

    const int KT = K/BK;

    auto load_slab = [&](int slot, int kt){
        char* sA = smem + slot*STB;
        char* sB = sA + SAB;
        const __half* Ag = Ablk + kt*BK;
        #pragma unroll
        for (int i = 0; i < 8; i++){
            int idx = i*128 + tid;
            int r = idx >> 3, c = idx & 7;
            cp_async16(sA + r*128 + ((c ^ (r & 7))<<4), Ag + (size_t)r*lda + c*8);
        }
        const __half* Bg = Bblk + kt*BK;
        #pragma unroll
        for (int i = 0; i < 8; i++){
            int idx = i*128 + tid;
            int r = idx >> 3, c = idx & 7;
            cp_async16(sB + r*128 + ((c ^ (r & 7))<<4), Bg + (size_t)r*ldb + c*8);
        }
    };

    load_slab(0, 0); cp_commit();
    if (KT > 1) load_slab(1, 1);
    cp_commit();

    const int g  = lane >> 3;
    const int li = lane & 7;

    // register double-buffered fragments
    unsigned af[2][4][4], bq[2][4][4];

    auto load_frags = [&](unsigned sA_u, unsigned sB_u, int ks, int buf){
        #pragma unroll
        for (int mt = 0; mt < 4; mt++){
            int row = m_off + mt*16 + li + (g & 1)*8;
            int ch  = ks*2 + (g >> 1);
            ldm_x4(af[buf][mt], sA_u + row*128 + ((ch ^ (row & 7))<<4));
        }
        #pragma unroll
        for (int np = 0; np < 4; np++){
            int row = n_off + np*16 + li + (g >> 1)*8;
            int ch  = ks*2 + (g & 1);
            ldm_x4(bq[buf][np], sB_u + row*128 + ((ch ^ (row & 7))<<4));
        }
    };

    for (int kt = 0; kt < KT; kt++){
        cp_wait<1>();
        __syncthreads();
        int kf = kt + 2;
        if (kf < KT) load_slab(kf % GSTAGES, kf);
        cp_commit();

        const unsigned sA_u = smem_u + (kt % GSTAGES)*STB;
        const unsigned sB_u = sA_u + SAB;

        load_frags(sA_u, sB_u, 0, 0);
        #pragma unroll
        for (int ks = 0; ks < 4; ks++){
            const int cur = ks & 1;
            if (ks < 3) load_frags(sA_u, sB_u, ks + 1, cur ^ 1);
            #pragma unroll
            for (int mt = 0; mt < 4; mt++)
                #pragma unroll
                for (int np = 0; np < 4; np++){
                    mma16(acc[mt][np*2+0], af[cur][mt], &bq[cur][np][0]);
                    mma16(acc[mt][np*2+1], af[cur][mt], &bq[cur][np][2]);
                }
        }
    }

    // ---- epilogue: stage C tile in smem, then coalesced uint4 stores ----
    cp_wait<0>();
    __syncthreads();
    __half* ctile = (__half*)smem;   // [BM][LDC_S]
    const int lr = lane >> 2, lc = lane & 3;

    #pragma unroll
    for (int mt = 0; mt < 4; mt++){
        #pragma unroll
        for (int nt = 0; nt < 8; nt++){
            int cl = n_off + nt*8 + lc*2;
            int cg = pn*BN + cl;
            #pragma unroll
            for (int half_ = 0; half_ < 2; half_++){
                int rl = m_off + mt*16 + lr + half_*8;
                float v0 = acc[mt][nt][half_*2+0];
                float v1 = acc[mt][nt][half_*2+1];
                __half2 hv;
                if constexpr (EPI == 1){
                    v0 += bias[cg]; v1 += bias[cg+1];
                    if (pn >= QKV3/BN)
                        hv = __floats2half2_rn(gelu_tanh(v0), gelu_tanh(v1));
                    else
                        hv = __floats2half2_rn(v0, v1);
                } else {
                    hv = __floats2half2_rn(v0, v1);
                }
                *(__half2*)&ctile[rl*LDC_S + cl] = hv;
            }
        }
    }
    __syncthreads();

    __half* dstbase;
    size_t stride;
    if constexpr (EPI == 1){
        if (pn >= QKV3/BN){ dstbase = (__half*)Cv2 + HID + (pn*BN - QKV3); stride = K2; }
        else              { dstbase = (__half*)Cv  + pn*BN;               stride = QKV3; }
    } else {
        dstbase = (__half*)Cv + (size_t)sk*NTOK*HID + pn*BN;
        stride = HID;
    }
    const int row0 = pm*BM;
    #pragma unroll
    for (int j = 0; j < 16; j++){
        int idx = j*128 + tid;
        int rl = idx >> 4;
        int q  = idx & 15;
        *(uint4*)&dstbase[(size_t)(row0+rl)*stride + q*8] =
            *(const uint4*)&ctile[rl*LDC_S + q*8];
    }
}

// ---------------- kernel: split-K reduce + bias + residual + gate ----------------
__global__ void __launch_bounds__(256, 4)
reduce_out(const __half* __restrict__ part,
           const float* __restrict__ x,
           const float* __restrict__ bias,
           const float* __restrict__ mod,
           float* __restrict__ out){
    size_t idx = (size_t)blockIdx.x*256 + threadIdx.x;
    int r = (int)(idx / (HID/4));
    int c = (int)(idx % (HID/4)) * 4;
    const float* gate = mod + (r >> 11)*MOD3 + 2*HID;
    float s0, s1, s2, s3;
    {
        float4 bv = *(const float4*)&bias[c];
        s0 = bv.x; s1 = bv.y; s2 = bv.z; s3 = bv.w;
    }
    #pragma unroll
    for (int p = 0; p < SPLITK; p++){
        uint2 u = *(const uint2*)&part[(size_t)p*NTOK*HID + (size_t)r*HID + c];
        __half2 h0 = *(__half2*)&u.x, h1 = *(__half2*)&u.y;
        float2 f0 = __half22float2(h0), f1 = __half22float2(h1);
        s0 += f0.x; s1 += f0.y; s2 += f1.x; s3 += f1.y;
    }
    float4 g4 = *(const float4*)&gate[c];
    float4 xv = *(const float4*)&x[(size_t)r*HID + c];
    float4 o;
    o.x = xv.x + g4.x*s0;
    o.y = xv.y + g4.y*s1;
    o.z = xv.z + g4.z*s2;
    o.w = xv.w + g4.w*s3;
    *(float4*)&out[(size_t)r*HID + c] = o;
}

// ---------------- kernel 4: per-token head-attention -> A2[:, :3072] ----------------
// sk re-strided to SKS=132 floats/row: lane-per-key score phase has only 3-way
// LDS conflicts (g, g+8, g+16) instead of full-warp; score dots use broadcast q.
#define SKS 132
__global__ void __launch_bounds__(256, 4)
attn_kernel(const __half* __restrict__ h,
            const float* __restrict__ pe,
            const float* __restrict__ qsc,
            const float* __restrict__ ksc,
            __half* __restrict__ a2){
    __shared__ float sq[NH*HD], sk[NH*SKS], sv[NH*HD], ss[NH*NH];
    const int t = blockIdx.x;
    const int b = t >> 11;
    const int l = t & 2047;
    const int tid = threadIdx.x;
    const int lane = tid & 31;
    const int w = tid >> 5;

    const __half* hrow = h + (size_t)t*QKV3;

    for (int j = tid; j < 2304; j += 256){
        uint2 u = ((const uint2*)hrow)[j];
        __half2 p0 = *(__half2*)&u.x, p1 = *(__half2*)&u.y;
        float2 f0 = __half22float2(p0), f1 = __half22float2(p1);
        float4 v4; v4.x = f0.x; v4.y = f0.y; v4.z = f1.x; v4.w = f1.y;
        if (j < 768){
            ((float4*)sq)[j] = v4;
        } else if (j < 1536){
            int o = j - 768;
            *(float4*)&sk[(o >> 5)*SKS + (o & 31)*4] = v4;
        } else {
            ((float4*)sv)[j - 1536] = v4;
        }
    }
    __syncthreads();

    const float* pet = pe + ((size_t)(b*LL + l))*(HD/2)*4;
    float4 qs4 = *(const float4*)&qsc[lane*4];
    float4 ks4 = *(const float4*)&ksc[lane*4];
    float4 e0 = *(const float4*)&pet[lane*8];
    float4 e1 = *(const float4*)&pet[lane*8 + 4];

    // rms norm + rope (warp w handles heads w, w+8, w+16)
    #pragma unroll
    for (int i = 0; i < 3; i++){
        int hh = w + 8*i;
        float4 q4 = *(float4*)&sq[hh*HD + lane*4];
        float4 k4 = *(float4*)&sk[hh*SKS + lane*4];
        float pq = q4.x*q4.x + q4.y*q4.y + q4.z*q4.z + q4.w*q4.w;
        float pk = k4.x*k4.x + k4.y*k4.y + k4.z*k4.z + k4.w*k4.w;
        #pragma unroll
        for (int o = 16; o > 0; o >>= 1){
            pq += __shfl_xor_sync(0xffffffffu, pq, o);
            pk += __shfl_xor_sync(0xffffffffu, pk, o);
        }
        float rq = rsqrtf(pq*(1.0f/HD) + 1e-6f);
        float rk = rsqrtf(pk*(1.0f/HD) + 1e-6f);
        q4.x *= rq*qs4.x; q4.y *= rq*qs4.y; q4.z *= rq*qs4.z; q4.w *= rq*qs4.w;
        k4.x *= rk*ks4.x; k4.y *= rk*ks4.y; k4.z *= rk*ks4.z; k4.w *= rk*ks4.w;
        float4 qo, ko;
        qo.x = e0.x*q4.x + e0.y*q4.y;  qo.y = e0.z*q4.x + e0.w*q4.y;
        qo.z = e1.x*q4.z + e1.y*q4.w;  qo.w = e1.z*q4.z + e1.w*q4.w;
        ko.x = e0.x*k4.x + e0.y*k4.y;  ko.y = e0.z*k4.x + e0.w*k4.y;
        ko.z = e1.x*k4.z + e1.y*k4.w;  ko.w = e1.z*k4.z + e1.w*k4.w;
        const float sc = 0.08838834764831845f; // 1/sqrt(128)
        qo.x *= sc; qo.y *= sc; qo.z *= sc; qo.w *= sc;
        *(float4*)&sq[hh*HD + lane*4] = qo;
        *(float4*)&sk[hh*SKS + lane*4] = ko;
    }
    __syncthreads();

    // scores + softmax: lane = key index g (lanes 24..31 idle-duplicate)
    const int g24 = (lane < NH) ? lane : 0;
    #pragma unroll
    for (int i = 0; i < 3; i++){
        int hh = w + 8*i;
        float s = 0.f;
        const float* qrow = &sq[hh*HD];
        const float* krow = &sk[g24*SKS];
        #pragma unroll 8
        for (int d4 = 0; d4 < 32; d4++){
            float4 qv = *(const float4*)&qrow[d4*4];   // broadcast LDS
            float4 kv = *(const float4*)&krow[d4*4];   // 3-way conflict max
            s += qv.x*kv.x + qv.y*kv.y + qv.z*kv.z + qv.w*kv.w;
        }
        float v = (lane < NH) ? s : -1e30f;
        float mx = v;
        #pragma unroll
        for (int o = 16; o > 0; o >>= 1) mx = fmaxf(mx, __shfl_xor_sync(0xffffffffu, mx, o));
        float e = (lane < NH) ? expf(v - mx) : 0.f;
        float sum = e;
        #pragma unroll
        for (int o = 16; o > 0; o >>= 1) sum += __shfl_xor_sync(0xffffffffu, sum, o);
        if (lane < NH) ss[hh*NH + lane] = e / sum;
    }
    __syncwarp();

    // attn out = probs @ V
    #pragma unroll
    for (int i = 0; i < 3; i++){
        int hh = w + 8*i;
        float4 accv; accv.x = accv.y = accv.z = accv.w = 0.f;
        #pragma unroll 8
        for (int gg = 0; gg < NH; gg++){
            float p = ss[hh*NH + gg];
            float4 vv = *(const float4*)&sv[gg*HD + lane*4];
            accv.x += p*vv.x; accv.y += p*vv.y; accv.z += p*vv.z; accv.w += p*vv.w;
        }
        __half2 p0 = __floats2half2_rn(accv.x, accv.y);
        __half2 p1 = __floats2half2_rn(accv.z, accv.w);
        uint2 u; u.x = *(unsigned*)&p0; u.y = *(unsigned*)&p1;
        *(uint2*)&a2[(size_t)t*K2 + hh*HD + lane*4] = u;
    }
}

// ---------------- launch ----------------
extern "C" void kernel_launch(void* const* d_in, const int* in_sizes, int n_in,
                              void* d_out, int out_size){
    const float* x      = (const float*)d_in[0];
    const float* vec    = (const float*)d_in[1];
    const float* pe     = (const float*)d_in[2];
    const float* mod_w  = (const float*)d_in[3];
    const float* mod_b  = (const float*)d_in[4];
    const float* lin1_w = (const float*)d_in[5];
    const float* lin1_b = (const float*)d_in[6];
    const float* lin2_w = (const float*)d_in[7];
    const float* lin2_b = (const float*)d_in[8];
    const float* q_scale= (const float*)d_in[9];
    const float* k_scale= (const float*)d_in[10];
    float* out = (float*)d_out;

    float *d_mod;
    __half *d_xh, *d_h, *d_a2h, *d_w1t, *d_w2t, *d_part;
    cudaGetSymbolAddress((void**)&d_mod,  g_mod);
    cudaGetSymbolAddress((void**)&d_xh,   g_xh);
    cudaGetSymbolAddress((void**)&d_h,    g_h);
    cudaGetSymbolAddress((void**)&d_a2h,  g_a2h);
    cudaGetSymbolAddress((void**)&d_w1t,  g_w1t);
    cudaGetSymbolAddress((void**)&d_w2t,  g_w2t);
    cudaGetSymbolAddress((void**)&d_part, g_part);

    cudaFuncSetAttribute(gemm_f16<1>, cudaFuncAttributeMaxDynamicSharedMemorySize, GEMM_SMEM);
    cudaFuncSetAttribute(gemm_f16<2>, cudaFuncAttributeMaxDynamicSharedMemorySize, GEMM_SMEM);

    // 0) transpose + fp16-round weights
    transpose_half<<<dim3(N1/64, HID/64), 256>>>(lin1_w, d_w1t, HID, N1);
    transpose_half<<<dim3(HID/64, K2/64), 256>>>(lin2_w, d_w2t, K2, HID);

    // 1) mod = silu(vec) @ mod_w + mod_b
    mod_kernel<<<dim3(MOD3/128, BB), 128>>>(vec, mod_w, mod_b, d_mod);

    // 2) x_mod = (1 + scale) * LN(x) + shift  (fp16 out)
    ln_mod_kernel<<<NTOK, 256>>>(x, d_mod, d_xh);

    // 3) h = x_mod @ lin1_w + lin1_b ; qkv -> g_h, gelu(mlp) -> g_a2h
    gemm_f16<1><<<(NTOK/BM)*(N1/BN), 128, GEMM_SMEM>>>(
        d_xh, HID, d_w1t, HID, lin1_b, d_h, NTOK, N1, HID, d_a2h);

    // 4) per-token attention -> A2[:, :3072]
    attn_kernel<<<NTOK, 256>>>(d_h, pe, q_scale, k_scale, d_a2h);

    // 5a) split-K partials: A2 @ lin2_w  (SPLITK=5 → 3840 CTAs ≈ 12.97 waves)
    gemm_f16<2><<<(NTOK/BM)*(HID/BN)*SPLITK, 128, GEMM_SMEM>>>(
        d_a2h, K2, d_w2t, K2, nullptr, d_part, NTOK, HID, KSPL, nullptr);

    // 5b) out = x + gate*(sum partials + bias)
    reduce_out<<<(NTOK*HID/4)/256, 256>>>(d_part, x, lin2_b, d_mod, out);
}

// round 15
// speedup vs baseline: 1.0561x; 1.0505x over previous
#include <cuda_runtime.h>
#include <cuda_fp16.h>
#include <cstdint>
#include <cmath>

// ---------------- problem constants ----------------
#define HID   3072
#define NH    24
#define HD    128
#define MLPD  12288
#define BB    2
#define LL    2048
#define NTOK  (BB*LL)            // 4096
#define N1    (3*HID + MLPD)     // 21504
#define K2    (HID + MLPD)       // 15360
#define MOD3  (3*HID)            // 9216
#define QKV3  (3*HID)            // 9216
#define SPLITK 5
#define KSPL  (K2/SPLITK)        // 3072

// ---------------- scratch (device globals; no runtime allocs) ----------------
__device__ float  g_mod [BB*MOD3];
__device__ __half g_xh  [(size_t)NTOK*HID];
__device__ __half g_h   [(size_t)NTOK*QKV3];   // qkv only
__device__ __half g_a2h [(size_t)NTOK*K2];
__device__ __half g_w1t [(size_t)N1*HID];      // lin1_w^T [N1, HID] fp16
__device__ __half g_w2t [(size_t)HID*K2];      // lin2_w^T [HID, K2] fp16
__device__ __half g_part[(size_t)SPLITK*NTOK*HID]; // split-K partials (fp16)

// ---------------- helpers ----------------
__device__ __forceinline__ void cp_async16(void* sptr, const void* gptr){
    unsigned sa = (unsigned)__cvta_generic_to_shared(sptr);
    asm volatile("cp.async.cg.shared.global [%0], [%1], 16;\n" :: "r"(sa), "l"(gptr));
}
__device__ __forceinline__ void cp_commit(){ asm volatile("cp.async.commit_group;\n"); }
template<int N> __device__ __forceinline__ void cp_wait(){ asm volatile("cp.async.wait_group %0;\n" :: "n"(N)); }

__device__ __forceinline__ float gelu_tanh(float x){
    float x3 = x*x*x;
    return 0.5f*x*(1.0f + tanhf(0.7978845608028654f*(x + 0.044715f*x3)));
}
__device__ __forceinline__ void ldm_x4(unsigned* r, unsigned addr){
    asm volatile("ldmatrix.sync.aligned.m8n8.x4.shared.b16 {%0,%1,%2,%3}, [%4];\n"
        : "=r"(r[0]), "=r"(r[1]), "=r"(r[2]), "=r"(r[3]) : "r"(addr));
}
__device__ __forceinline__ void mma16(float* c, const unsigned* a, const unsigned* b){
    asm volatile("mma.sync.aligned.m16n8k16.row.col.f32.f16.f16.f32 "
        "{%0,%1,%2,%3}, {%4,%5,%6,%7}, {%8,%9}, {%0,%1,%2,%3};\n"
        : "+f"(c[0]), "+f"(c[1]), "+f"(c[2]), "+f"(c[3])
        : "r"(a[0]), "r"(a[1]), "r"(a[2]), "r"(a[3]), "r"(b[0]), "r"(b[1]));
}

// ---------------- kernel 0: transpose + fp16-round weights (64x64, vectorized) ----------------
__global__ void __launch_bounds__(256, 6)
transpose_half(const float* __restrict__ in, __half* __restrict__ out,
               int K, int N){
    __shared__ float tile[64][65];
    int n0 = blockIdx.x*64, k0 = blockIdx.y*64;
    int tx = threadIdx.x & 15;
    int ty = threadIdx.x >> 4;
    #pragma unroll
    for (int p = 0; p < 4; p++){
        int k = ty + p*16;
        float4 v = *(const float4*)&in[(size_t)(k0+k)*N + n0 + tx*4];
        tile[k][tx*4+0] = v.x;
        tile[k][tx*4+1] = v.y;
        tile[k][tx*4+2] = v.z;
        tile[k][tx*4+3] = v.w;
    }
    __syncthreads();
    int cx = threadIdx.x & 7;
    int cy = threadIdx.x >> 3;
    #pragma unroll
    for (int p = 0; p < 2; p++){
        int n = cy + p*32;
        __half hbuf[8];
        #pragma unroll
        for (int i = 0; i < 8; i++)
            hbuf[i] = __float2half_rn(tile[cx*8+i][n]);
        *(uint4*)&out[(size_t)(n0+n)*K + k0 + cx*8] = *(uint4*)hbuf;
    }
}

// ---------------- kernel 1: mod = silu(vec) @ mod_w + mod_b (4-way K-split) ----------------
#define MODKS 768   // K slice per thread group (3072/4)
__global__ void __launch_bounds__(256, 4)
mod_kernel(const float* __restrict__ vec,
           const float* __restrict__ W,
           const float* __restrict__ bias,
           float* __restrict__ mod){
    __shared__ float sv[HID];
    __shared__ float red[256];
    int b = blockIdx.y;
    int tid = threadIdx.x;
    for (int i = tid; i < HID; i += 256){
        float v = vec[b*HID + i];
        sv[i] = v / (1.0f + expf(-v));
    }
    __syncthreads();
    int jloc  = tid & 63;
    int kpart = tid >> 6;            // 0..3
    int j = blockIdx.x*64 + jloc;
    const float* w = W + (size_t)(kpart*MODKS)*MOD3 + j;
    const float* s = sv + kpart*MODKS;
    float a0 = 0.f, a1 = 0.f, a2 = 0.f, a3 = 0.f;
    #pragma unroll 4
    for (int k = 0; k < MODKS; k += 4){
        a0 += s[k  ] * w[(size_t)(k  )*MOD3];
        a1 += s[k+1] * w[(size_t)(k+1)*MOD3];
        a2 += s[k+2] * w[(size_t)(k+2)*MOD3];
        a3 += s[k+3] * w[(size_t)(k+3)*MOD3];
    }
    red[tid] = (a0+a1)+(a2+a3);
    __syncthreads();
    if (kpart == 0)
        mod[b*MOD3 + j] = bias[j] + ((red[jloc] + red[jloc+64]) + (red[jloc+128] + red[jloc+192]));
}

// ---------------- kernel 2: x_mod = (1+scale)*LN(x) + shift  -> fp16 ----------------
__global__ void ln_mod_kernel(const float* __restrict__ x,
                              const float* __restrict__ mod,
                              __half* __restrict__ xh){
    int t = blockIdx.x;
    int b = t >> 11;
    const float4* xr = (const float4*)(x + (size_t)t*HID);
    float4 v[3];
    float s = 0.f, s2 = 0.f;
    #pragma unroll
    for (int i = 0; i < 3; i++){
        v[i] = xr[threadIdx.x + i*256];
        s  += v[i].x + v[i].y + v[i].z + v[i].w;
        s2 += v[i].x*v[i].x + v[i].y*v[i].y + v[i].z*v[i].z + v[i].w*v[i].w;
    }
    int lane = threadIdx.x & 31, w = threadIdx.x >> 5;
    #pragma unroll
    for (int o = 16; o > 0; o >>= 1){
        s  += __shfl_xor_sync(0xffffffffu, s,  o);
        s2 += __shfl_xor_sync(0xffffffffu, s2, o);
    }
    __shared__ float red[64];
    if (lane == 0){ red[w] = s; red[32+w] = s2; }
    __syncthreads();
    float ts = 0.f, ts2 = 0.f;
    #pragma unroll
    for (int i = 0; i < 8; i++){ ts += red[i]; ts2 += red[32+i]; }
    float mu  = ts  * (1.0f/HID);
    float var = ts2 * (1.0f/HID) - mu*mu;
    float rr  = rsqrtf(var + 1e-6f);

    const float* shiftp = mod + b*MOD3;
    const float* scalep = shiftp + HID;
    uint2* dst = (uint2*)(xh + (size_t)t*HID);
    #pragma unroll
    for (int i = 0; i < 3; i++){
        int j = threadIdx.x + i*256;
        float4 sh = ((const float4*)shiftp)[j];
        float4 sc = ((const float4*)scalep)[j];
        float ox = (1.f+sc.x)*((v[i].x-mu)*rr) + sh.x;
        float oy = (1.f+sc.y)*((v[i].y-mu)*rr) + sh.y;
        float oz = (1.f+sc.z)*((v[i].z-mu)*rr) + sh.z;
        float ow = (1.f+sc.w)*((v[i].w-mu)*rr) + sh.w;
        __half2 p0 = __floats2half2_rn(ox, oy);
        __half2 p1 = __floats2half2_rn(oz, ow);
        uint2 u; u.x = *(unsigned*)&p0; u.y = *(unsigned*)&p1;
        dst[j] = u;
    }
}

// ---------------- fp16 mma.sync GEMM (128x128 tile, 4 warps, 2 CTAs/SM) ----------------
#define BM 128
#define BN 128
#define BK 64
#define GSTAGES 3
#define SAB (BM*128)             // 16384 B
#define SBB (BN*128)             // 16384 B
#define STB (SAB+SBB)            // 32768 B
#define GEMM_SMEM (GSTAGES*STB)  // 98304 B
#define GROUP_M 32
#define LDC_S 136                // smem C-tile row stride in halves (conflict-free)

template<int EPI>
__global__ void __launch_bounds__(128, 2)
gemm_f16(const __half* __restrict__ A, int lda,
         const __half* __restrict__ Bt, int ldb,
         const float* __restrict__ bias,
         void* __restrict__ Cv,
         int M, int N, int K,
         void* __restrict__ Cv2){
    extern __shared__ char smem[];
    const unsigned smem_u = (unsigned)__cvta_generic_to_shared(smem);
    const int tid  = threadIdx.x;
    const int lane = tid & 31;
    const int wid  = tid >> 5;
    const int m_off = (wid & 1)*64;
    const int n_off = (wid >> 1)*64;

    int npm = M/BM, npn = N/BN;
    int tiles = npm*npn;
    int bx = blockIdx.x;
    int sk = 0;
    if constexpr (EPI == 2){ sk = bx / tiles; bx = bx % tiles; }

    int pig = GROUP_M*npn;
    int gidg = bx / pig;
    int first = gidg*GROUP_M;
    int gsz = (npm - first < GROUP_M) ? (npm - first) : GROUP_M;
    int inGroup = bx % pig;
    int pm = first + (inGroup % gsz);
    int pn = inGroup / gsz;

    const __half* Ablk = A  + (size_t)(pm*BM)*lda + (EPI==2 ? sk*KSPL : 0);
    const __half* Bblk = Bt + (size_t)(pn*BN)*ldb + (EPI==2 ? sk*KSPL : 0);

    float acc[4][8][4];
    #pragma unroll
    for (int a = 0; a < 4; a++)
        #pragma unroll
        for (int b = 0; b < 8; b++)
            #pragma unroll
            for (int c = 0; c < 4; c++) acc[a][b][c] = 0.f;

    const int KT = K/BK;

    auto load_slab = [&](int slot, int kt){
        char* sA = smem + slot*STB;
        char* sB = sA + SAB;
        const __half* Ag = Ablk + kt*BK;
        #pragma unroll
        for (int i = 0; i < 8; i++){
            int idx = i*128 + tid;
            int r = idx >> 3, c = idx & 7;
            cp_async16(sA + r*128 + ((c ^ (r & 7))<<4), Ag + (size_t)r*lda + c*8);
        }
        const __half* Bg = Bblk + kt*BK;
        #pragma unroll
        for (int i = 0; i < 8; i++){
            int idx = i*128 + tid;
            int r = idx >> 3, c = idx & 7;
            cp_async16(sB + r*128 + ((c ^ (r & 7))<<4), Bg + (size_t)r*ldb + c*8);
        }
    };

    load_slab(0, 0); cp_commit();
    if (KT > 1) load_slab(1, 1);
    cp_commit();

    const int g  = lane >> 3;
    const int li = lane & 7;

    unsigned af[2][4][4], bq[2][4][4];

    auto load_frags = [&](unsigned sA_u, unsigned sB_u, int ks, int buf){
        #pragma unroll
        for (int mt = 0; mt < 4; mt++){
            int row = m_off + mt*16 + li + (g & 1)*8;
            int ch  = ks*2 + (g >> 1);
            ldm_x4(af[buf][mt], sA_u + row*128 + ((ch ^ (row & 7))<<4));
        }
        #pragma unroll
        for (int np = 0; np < 4; np++){
            int row = n_off + np*16 + li + (g >> 1)*8;
            int ch  = ks*2 + (g & 1);
            ldm_x4(bq[buf][np], sB_u + row*128 + ((ch ^ (row & 7))<<4));
        }
    };

    for (int kt = 0; kt < KT; kt++){
        cp_wait<1>();
        __syncthreads();
        int kf = kt + 2;
        if (kf < KT) load_slab(kf % GSTAGES, kf);
        cp_commit();

        const unsigned sA_u = smem_u + (kt % GSTAGES)*STB;
        const unsigned sB_u = sA_u + SAB;

        load_frags(sA_u, sB_u, 0, 0);
        #pragma unroll
        for (int ks = 0; ks < 4; ks++){
            const int cur = ks & 1;
            if (ks < 3) load_frags(sA_u, sB_u, ks + 1, cur ^ 1);
            #pragma unroll
            for (int mt = 0; mt < 4; mt++)
                #pragma unroll
                for (int np = 0; np < 4; np++){
                    mma16(acc[mt][np*2+0], af[cur][mt], &bq[cur][np][0]);
                    mma16(acc[mt][np*2+1], af[cur][mt], &bq[cur][np][2]);
                }
        }
    }

    // ---- epilogue: stage C tile in smem, then coalesced uint4 stores ----
    cp_wait<0>();
    __syncthreads();
    __half* ctile = (__half*)smem;   // [BM][LDC_S]
    const int lr = lane >> 2, lc = lane & 3;

    #pragma unroll
    for (int mt = 0; mt < 4; mt++){
        #pragma unroll
        for (int nt = 0; nt < 8; nt++){
            int cl = n_off + nt*8 + lc*2;
            int cg = pn*BN + cl;
            #pragma unroll
            for (int half_ = 0; half_ < 2; half_++){
                int rl = m_off + mt*16 + lr + half_*8;
                float v0 = acc[mt][nt][half_*2+0];
                float v1 = acc[mt][nt][half_*2+1];
                __half2 hv;
                if constexpr (EPI == 1){
                    v0 += bias[cg]; v1 += bias[cg+1];
                    if (pn >= QKV3/BN)
                        hv = __floats2half2_rn(gelu_tanh(v0), gelu_tanh(v1));
                    else
                        hv = __floats2half2_rn(v0, v1);
                } else {
                    hv = __floats2half2_rn(v0, v1);
                }
                *(__half2*)&ctile[rl*LDC_S + cl] = hv;
            }
        }
    }
    __syncthreads();

    __half* dstbase;
    size_t stride;
    if constexpr (EPI == 1){
        if (pn >= QKV3/BN){ dstbase = (__half*)Cv2 + HID + (pn*BN - QKV3); stride = K2; }
        else              { dstbase = (__half*)Cv  + pn*BN;               stride = QKV3; }
    } else {
        dstbase = (__half*)Cv + (size_t)sk*NTOK*HID + pn*BN;
        stride = HID;
    }
    const int row0 = pm*BM;
    #pragma unroll
    for (int j = 0; j < 16; j++){
        int idx = j*128 + tid;
        int rl = idx >> 4;
        int q  = idx & 15;
        *(uint4*)&dstbase[(size_t)(row0+rl)*stride + q*8] =
            *(const uint4*)&ctile[rl*LDC_S + q*8];
    }
}

// ---------------- kernel: split-K reduce + bias + residual + gate ----------------
__global__ void __launch_bounds__(256, 8)
reduce_out(const __half* __restrict__ part,
           const float* __restrict__ x,
           const float* __restrict__ bias,
           const float* __restrict__ mod,
           float* __restrict__ out){
    size_t idx = (size_t)blockIdx.x*256 + threadIdx.x;
    int r = (int)(idx / (HID/4));
    int c = (int)(idx % (HID/4)) * 4;
    const float* gate = mod + (r >> 11)*MOD3 + 2*HID;
    float s0, s1, s2, s3;
    {
        float4 bv = *(const float4*)&bias[c];
        s0 = bv.x; s1 = bv.y; s2 = bv.z; s3 = bv.w;
    }
    #pragma unroll
    for (int p = 0; p < SPLITK; p++){
        uint2 u = *(const uint2*)&part[(size_t)p*NTOK*HID + (size_t)r*HID + c];
        __half2 h0 = *(__half2*)&u.x, h1 = *(__half2*)&u.y;
        float2 f0 = __half22float2(h0), f1 = __half22float2(h1);
        s0 += f0.x; s1 += f0.y; s2 += f1.x; s3 += f1.y;
    }
    float4 g4 = *(const float4*)&gate[c];
    float4 xv = *(const float4*)&x[(size_t)r*HID + c];
    float4 o;
    o.x = xv.x + g4.x*s0;
    o.y = xv.y + g4.y*s1;
    o.z = xv.z + g4.z*s2;
    o.w = xv.w + g4.w*s3;
    *(float4*)&out[(size_t)r*HID + c] = o;
}

// ---------------- kernel 4: per-token head-attention -> A2[:, :3072] ----------------
#define SKS 132
__global__ void __launch_bounds__(256, 4)
attn_kernel(const __half* __restrict__ h,
            const float* __restrict__ pe,
            const float* __restrict__ qsc,
            const float* __restrict__ ksc,
            __half* __restrict__ a2){
    __shared__ float sq[NH*HD], sk[NH*SKS], sv[NH*HD], ss[NH*NH];
    const int t = blockIdx.x;
    const int b = t >> 11;
    const int l = t & 2047;
    const int tid = threadIdx.x;
    const int lane = tid & 31;
    const int w = tid >> 5;

    const __half* hrow = h + (size_t)t*QKV3;

    for (int j = tid; j < 2304; j += 256){
        uint2 u = ((const uint2*)hrow)[j];
        __half2 p0 = *(__half2*)&u.x, p1 = *(__half2*)&u.y;
        float2 f0 = __half22float2(p0), f1 = __half22float2(p1);
        float4 v4; v4.x = f0.x; v4.y = f0.y; v4.z = f1.x; v4.w = f1.y;
        if (j < 768){
            ((float4*)sq)[j] = v4;
        } else if (j < 1536){
            int o = j - 768;
            *(float4*)&sk[(o >> 5)*SKS + (o & 31)*4] = v4;
        } else {
            ((float4*)sv)[j - 1536] = v4;
        }
    }
    __syncthreads();

    const float* pet = pe + ((size_t)(b*LL + l))*(HD/2)*4;
    float4 qs4 = *(const float4*)&qsc[lane*4];
    float4 ks4 = *(const float4*)&ksc[lane*4];
    float4 e0 = *(const float4*)&pet[lane*8];
    float4 e1 = *(const float4*)&pet[lane*8 + 4];

    #pragma unroll
    for (int i = 0; i < 3; i++){
        int hh = w + 8*i;
        float4 q4 = *(float4*)&sq[hh*HD + lane*4];
        float4 k4 = *(float4*)&sk[hh*SKS + lane*4];
        float pq = q4.x*q4.x + q4.y*q4.y + q4.z*q4.z + q4.w*q4.w;
        float pk = k4.x*k4.x + k4.y*k4.y + k4.z*k4.z + k4.w*k4.w;
        #pragma unroll
        for (int o = 16; o > 0; o >>= 1){
            pq += __shfl_xor_sync(0xffffffffu, pq, o);
            pk += __shfl_xor_sync(0xffffffffu, pk, o);
        }
        float rq = rsqrtf(pq*(1.0f/HD) + 1e-6f);
        float rk = rsqrtf(pk*(1.0f/HD) + 1e-6f);
        q4.x *= rq*qs4.x; q4.y *= rq*qs4.y; q4.z *= rq*qs4.z; q4.w *= rq*qs4.w;
        k4.x *= rk*ks4.x; k4.y *= rk*ks4.y; k4.z *= rk*ks4.z; k4.w *= rk*ks4.w;
        float4 qo, ko;
        qo.x = e0.x*q4.x + e0.y*q4.y;  qo.y = e0.z*q4.x + e0.w*q4.y;
        qo.z = e1.x*q4.z + e1.y*q4.w;  qo.w = e1.z*q4.z + e1.w*q4.w;
        ko.x = e0.x*k4.x + e0.y*k4.y;  ko.y = e0.z*k4.x + e0.w*k4.y;
        ko.z = e1.x*k4.z + e1.y*k4.w;  ko.w = e1.z*k4.z + e1.w*k4.w;
        const float sc = 0.08838834764831845f; // 1/sqrt(128)
        qo.x *= sc; qo.y *= sc; qo.z *= sc; qo.w *= sc;
        *(float4*)&sq[hh*HD + lane*4] = qo;
        *(float4*)&sk[hh*SKS + lane*4] = ko;
    }
    __syncthreads();

    const int g24 = (lane < NH) ? lane : 0;
    #pragma unroll
    for (int i = 0; i < 3; i++){
        int hh = w + 8*i;
        float s = 0.f;
        const float* qrow = &sq[hh*HD];
        const float* krow = &sk[g24*SKS];
        #pragma unroll 8
        for (int d4 = 0; d4 < 32; d4++){
            float4 qv = *(const float4*)&qrow[d4*4];
            float4 kv = *(const float4*)&krow[d4*4];
            s += qv.x*kv.x + qv.y*kv.y + qv.z*kv.z + qv.w*kv.w;
        }
        float v = (lane < NH) ? s : -1e30f;
        float mx = v;
        #pragma unroll
        for (int o = 16; o > 0; o >>= 1) mx = fmaxf(mx, __shfl_xor_sync(0xffffffffu, mx, o));
        float e = (lane < NH) ? expf(v - mx) : 0.f;
        float sum = e;
        #pragma unroll
        for (int o = 16; o > 0; o >>= 1) sum += __shfl_xor_sync(0xffffffffu, sum, o);
        if (lane < NH) ss[hh*NH + lane] = e / sum;
    }
    __syncwarp();

    #pragma unroll
    for (int i = 0; i < 3; i++){
        int hh = w + 8*i;
        float4 accv; accv.x = accv.y = accv.z = accv.w = 0.f;
        #pragma unroll 8
        for (int gg = 0; gg < NH; gg++){
            float p = ss[hh*NH + gg];
            float4 vv = *(const float4*)&sv[gg*HD + lane*4];
            accv.x += p*vv.x; accv.y += p*vv.y; accv.z += p*vv.z; accv.w += p*vv.w;
        }
        __half2 p0 = __floats2half2_rn(accv.x, accv.y);
        __half2 p1 = __floats2half2_rn(accv.z, accv.w);
        uint2 u; u.x = *(unsigned*)&p0; u.y = *(unsigned*)&p1;
        *(uint2*)&a2[(size_t)t*K2 + hh*HD + lane*4] = u;
    }
}

// ---------------- launch ----------------
extern "C" void kernel_launch(void* const* d_in, const int* in_sizes, int n_in,
                              void* d_out, int out_size){
    const float* x      = (const float*)d_in[0];
    const float* vec    = (const float*)d_in[1];
    const float* pe     = (const float*)d_in[2];
    const float* mod_w  = (const float*)d_in[3];
    const float* mod_b  = (const float*)d_in[4];
    const float* lin1_w = (const float*)d_in[5];
    const float* lin1_b = (const float*)d_in[6];
    const float* lin2_w = (const float*)d_in[7];
    const float* lin2_b = (const float*)d_in[8];
    const float* q_scale= (const float*)d_in[9];
    const float* k_scale= (const float*)d_in[10];
    float* out = (float*)d_out;

    float *d_mod;
    __half *d_xh, *d_h, *d_a2h, *d_w1t, *d_w2t, *d_part;
    cudaGetSymbolAddress((void**)&d_mod,  g_mod);
    cudaGetSymbolAddress((void**)&d_xh,   g_xh);
    cudaGetSymbolAddress((void**)&d_h,    g_h);
    cudaGetSymbolAddress((void**)&d_a2h,  g_a2h);
    cudaGetSymbolAddress((void**)&d_w1t,  g_w1t);
    cudaGetSymbolAddress((void**)&d_w2t,  g_w2t);
    cudaGetSymbolAddress((void**)&d_part, g_part);

    cudaFuncSetAttribute(gemm_f16<1>, cudaFuncAttributeMaxDynamicSharedMemorySize, GEMM_SMEM);
    cudaFuncSetAttribute(gemm_f16<2>, cudaFuncAttributeMaxDynamicSharedMemorySize, GEMM_SMEM);

    // 0) transpose + fp16-round weights
    transpose_half<<<dim3(N1/64, HID/64), 256>>>(lin1_w, d_w1t, HID, N1);
    transpose_half<<<dim3(HID/64, K2/64), 256>>>(lin2_w, d_w2t, K2, HID);

    // 1) mod = silu(vec) @ mod_w + mod_b   (288 CTAs, 4-way K split)
    mod_kernel<<<dim3(MOD3/64, BB), 256>>>(vec, mod_w, mod_b, d_mod);

    // 2) x_mod = (1 + scale) * LN(x) + shift  (fp16 out)
    ln_mod_kernel<<<NTOK, 256>>>(x, d_mod, d_xh);

    // 3) h = x_mod @ lin1_w + lin1_b ; qkv -> g_h, gelu(mlp) -> g_a2h
    gemm_f16<1><<<(NTOK/BM)*(N1/BN), 128, GEMM_SMEM>>>(
        d_xh, HID, d_w1t, HID, lin1_b, d_h, NTOK, N1, HID, d_a2h);

    // 4) per-token attention -> A2[:, :3072]
    attn_kernel<<<NTOK, 256>>>(d_h, pe, q_scale, k_scale, d_a2h);

    // 5a) split-K partials: A2 @ lin2_w  (SPLITK=5 → 3840 CTAs ≈ 12.97 waves)
    gemm_f16<2><<<(NTOK/BM)*(HID/BN)*SPLITK, 128, GEMM_SMEM>>>(
        d_a2h, K2, d_w2t, K2, nullptr, d_part, NTOK, HID, KSPL, nullptr);

    // 5b) out = x + gate*(sum partials + bias)
    reduce_out<<<(NTOK*HID/4)/256, 256>>>(d_part, x, lin2_b, d_mod, out);
}

// round 16
// speedup vs baseline: 1.0652x; 1.0087x over previous
#include <cuda_runtime.h>
#include <cuda_fp16.h>
#include <cstdint>
#include <cmath>

// ---------------- problem constants ----------------
#define HID   3072
#define NH    24
#define HD    128
#define MLPD  12288
#define BB    2
#define LL    2048
#define NTOK  (BB*LL)            // 4096
#define N1    (3*HID + MLPD)     // 21504
#define K2    (HID + MLPD)       // 15360
#define MOD3  (3*HID)            // 9216
#define QKV3  (3*HID)            // 9216
#define SPLITK 5
#define KSPL  (K2/SPLITK)        // 3072

// ---------------- scratch (device globals; no runtime allocs) ----------------
__device__ float  g_mod [BB*MOD3];
__device__ __half g_xh  [(size_t)NTOK*HID];
__device__ __half g_h   [(size_t)NTOK*QKV3];   // qkv only
__device__ __half g_a2h [(size_t)NTOK*K2];
__device__ __half g_w1t [(size_t)N1*HID];      // lin1_w^T [N1, HID] fp16
__device__ __half g_w2t [(size_t)HID*K2];      // lin2_w^T [HID, K2] fp16
__device__ __half g_part[(size_t)SPLITK*NTOK*HID]; // split-K partials (fp16)

// ---------------- helpers ----------------
__device__ __forceinline__ void cp_async16(void* sptr, const void* gptr){
    unsigned sa = (unsigned)__cvta_generic_to_shared(sptr);
    asm volatile("cp.async.cg.shared.global [%0], [%1], 16;\n" :: "r"(sa), "l"(gptr));
}
__device__ __forceinline__ void cp_commit(){ asm volatile("cp.async.commit_group;\n"); }
template<int N> __device__ __forceinline__ void cp_wait(){ asm volatile("cp.async.wait_group %0;\n" :: "n"(N)); }

__device__ __forceinline__ float gelu_tanh(float x){
    float x3 = x*x*x;
    return 0.5f*x*(1.0f + tanhf(0.7978845608028654f*(x + 0.044715f*x3)));
}
__device__ __forceinline__ void ldm_x4(unsigned* r, unsigned addr){
    asm volatile("ldmatrix.sync.aligned.m8n8.x4.shared.b16 {%0,%1,%2,%3}, [%4];\n"
        : "=r"(r[0]), "=r"(r[1]), "=r"(r[2]), "=r"(r[3]) : "r"(addr));
}
__device__ __forceinline__ void mma16(float* c, const unsigned* a, const unsigned* b){
    asm volatile("mma.sync.aligned.m16n8k16.row.col.f32.f16.f16.f32 "
        "{%0,%1,%2,%3}, {%4,%5,%6,%7}, {%8,%9}, {%0,%1,%2,%3};\n"
        : "+f"(c[0]), "+f"(c[1]), "+f"(c[2]), "+f"(c[3])
        : "r"(a[0]), "r"(a[1]), "r"(a[2]), "r"(a[3]), "r"(b[0]), "r"(b[1]));
}

// ---------------- kernel 0: transpose + fp16-round weights (64x64, vectorized) ----------------
__global__ void __launch_bounds__(256, 6)
transpose_half(const float* __restrict__ in, __half* __restrict__ out,
               int K, int N){
    __shared__ float tile[64][65];
    int n0 = blockIdx.x*64, k0 = blockIdx.y*64;
    int tx = threadIdx.x & 15;
    int ty = threadIdx.x >> 4;
    #pragma unroll
    for (int p = 0; p < 4; p++){
        int k = ty + p*16;
        float4 v = *(const float4*)&in[(size_t)(k0+k)*N + n0 + tx*4];
        tile[k][tx*4+0] = v.x;
        tile[k][tx*4+1] = v.y;
        tile[k][tx*4+2] = v.z;
        tile[k][tx*4+3] = v.w;
    }
    __syncthreads();
    int cx = threadIdx.x & 7;
    int cy = threadIdx.x >> 3;
    #pragma unroll
    for (int p = 0; p < 2; p++){
        int n = cy + p*32;
        __half hbuf[8];
        #pragma unroll
        for (int i = 0; i < 8; i++)
            hbuf[i] = __float2half_rn(tile[cx*8+i][n]);
        *(uint4*)&out[(size_t)(n0+n)*K + k0 + cx*8] = *(uint4*)hbuf;
    }
}

// ---------------- kernel 1: mod = silu(vec) @ mod_w + mod_b (4-way K-split) ----------------
#define MODKS 768   // K slice per thread group (3072/4)
__global__ void __launch_bounds__(256, 4)
mod_kernel(const float* __restrict__ vec,
           const float* __restrict__ W,
           const float* __restrict__ bias,
           float* __restrict__ mod){
    __shared__ float sv[HID];
    __shared__ float red[256];
    int b = blockIdx.y;
    int tid = threadIdx.x;
    for (int i = tid; i < HID; i += 256){
        float v = vec[b*HID + i];
        sv[i] = v / (1.0f + expf(-v));
    }
    __syncthreads();
    int jloc  = tid & 63;
    int kpart = tid >> 6;            // 0..3
    int j = blockIdx.x*64 + jloc;
    const float* w = W + (size_t)(kpart*MODKS)*MOD3 + j;
    const float* s = sv + kpart*MODKS;
    float a0 = 0.f, a1 = 0.f, a2 = 0.f, a3 = 0.f;
    #pragma unroll 4
    for (int k = 0; k < MODKS; k += 4){
        a0 += s[k  ] * w[(size_t)(k  )*MOD3];
        a1 += s[k+1] * w[(size_t)(k+1)*MOD3];
        a2 += s[k+2] * w[(size_t)(k+2)*MOD3];
        a3 += s[k+3] * w[(size_t)(k+3)*MOD3];
    }
    red[tid] = (a0+a1)+(a2+a3);
    __syncthreads();
    if (kpart == 0)
        mod[b*MOD3 + j] = bias[j] + ((red[jloc] + red[jloc+64]) + (red[jloc+128] + red[jloc+192]));
}

// ---------------- kernel 2: x_mod = (1+scale)*LN(x) + shift  -> fp16 ----------------
__global__ void ln_mod_kernel(const float* __restrict__ x,
                              const float* __restrict__ mod,
                              __half* __restrict__ xh){
    int t = blockIdx.x;
    int b = t >> 11;
    const float4* xr = (const float4*)(x + (size_t)t*HID);
    float4 v[3];
    float s = 0.f, s2 = 0.f;
    #pragma unroll
    for (int i = 0; i < 3; i++){
        v[i] = xr[threadIdx.x + i*256];
        s  += v[i].x + v[i].y + v[i].z + v[i].w;
        s2 += v[i].x*v[i].x + v[i].y*v[i].y + v[i].z*v[i].z + v[i].w*v[i].w;
    }
    int lane = threadIdx.x & 31, w = threadIdx.x >> 5;
    #pragma unroll
    for (int o = 16; o > 0; o >>= 1){
        s  += __shfl_xor_sync(0xffffffffu, s,  o);
        s2 += __shfl_xor_sync(0xffffffffu, s2, o);
    }
    __shared__ float red[64];
    if (lane == 0){ red[w] = s; red[32+w] = s2; }
    __syncthreads();
    float ts = 0.f, ts2 = 0.f;
    #pragma unroll
    for (int i = 0; i < 8; i++){ ts += red[i]; ts2 += red[32+i]; }
    float mu  = ts  * (1.0f/HID);
    float var = ts2 * (1.0f/HID) - mu*mu;
    float rr  = rsqrtf(var + 1e-6f);

    const float* shiftp = mod + b*MOD3;
    const float* scalep = shiftp + HID;
    uint2* dst = (uint2*)(xh + (size_t)t*HID);
    #pragma unroll
    for (int i = 0; i < 3; i++){
        int j = threadIdx.x + i*256;
        float4 sh = ((const float4*)shiftp)[j];
        float4 sc = ((const float4*)scalep)[j];
        float ox = (1.f+sc.x)*((v[i].x-mu)*rr) + sh.x;
        float oy = (1.f+sc.y)*((v[i].y-mu)*rr) + sh.y;
        float oz = (1.f+sc.z)*((v[i].z-mu)*rr) + sh.z;
        float ow = (1.f+sc.w)*((v[i].w-mu)*rr) + sh.w;
        __half2 p0 = __floats2half2_rn(ox, oy);
        __half2 p1 = __floats2half2_rn(oz, ow);
        uint2 u; u.x = *(unsigned*)&p0; u.y = *(unsigned*)&p1;
        dst[j] = u;
    }
}

// ---------------- fp16 mma.sync GEMM (128x128 tile, 4 warps, 2 CTAs/SM) ----------------
#define BM 128
#define BN 128
#define BK 64
#define GSTAGES 3
#define SAB (BM*128)             // 16384 B
#define SBB (BN*128)             // 16384 B
#define STB (SAB+SBB)            // 32768 B
#define GEMM_SMEM (GSTAGES*STB)  // 98304 B
#define GROUP_M 32
#define LDC_S 136                // smem C-tile row stride in halves (conflict-free)

template<int EPI>
__global__ void __launch_bounds__(128, 2)
gemm_f16(const __half* __restrict__ A, int lda,
         const __half* __restrict__ Bt, int ldb,
         const float* __restrict__ bias,
         void* __restrict__ Cv,
         int M, int N, int K,
         void* __restrict__ Cv2){
    extern __shared__ char smem[];
    const unsigned smem_u = (unsigned)__cvta_generic_to_shared(smem);
    const int tid  = threadIdx.x;
    const int lane = tid & 31;
    const int wid  = tid >> 5;
    const int m_off = (wid & 1)*64;
    const int n_off = (wid >> 1)*64;

    int npm = M/BM, npn = N/BN;
    int tiles = npm*npn;
    int bx = blockIdx.x;
    int sk = 0;
    if constexpr (EPI == 2){ sk = bx / tiles; bx = bx % tiles; }

    int pig = GROUP_M*npn;
    int gidg = bx / pig;
    int first = gidg*GROUP_M;
    int gsz = (npm - first < GROUP_M) ? (npm - first) : GROUP_M;
    int inGroup = bx % pig;
    int pm = first + (inGroup % gsz);
    int pn = inGroup / gsz;

    const __half* Ablk = A  + (size_t)(pm*BM)*lda + (EPI==2 ? sk*KSPL : 0);
    const __half* Bblk = Bt + (size_t)(pn*BN)*ldb + (EPI==2 ? sk*KSPL : 0);

    float acc[4][8][4];
    #pragma unroll
    for (int a = 0; a < 4; a++)
        #pragma unroll
        for (int b = 0; b < 8; b++)
            #pragma unroll
            for (int c = 0; c < 4; c++) acc[a][b][c] = 0.f;

    const int KT = K/BK;

    auto load_slab = [&](int slot, int kt){
        char* sA = smem + slot*STB;
        char* sB = sA + SAB;
        const __half* Ag = Ablk + kt*BK;
        #pragma unroll
        for (int i = 0; i < 8; i++){
            int idx = i*128 + tid;
            int r = idx >> 3, c = idx & 7;
            cp_async16(sA + r*128 + ((c ^ (r & 7))<<4), Ag + (size_t)r*lda + c*8);
        }
        const __half* Bg = Bblk + kt*BK;
        #pragma unroll
        for (int i = 0; i < 8; i++){
            int idx = i*128 + tid;
            int r = idx >> 3, c = idx & 7;
            cp_async16(sB + r*128 + ((c ^ (r & 7))<<4), Bg + (size_t)r*ldb + c*8);
        }
    };

    load_slab(0, 0); cp_commit();
    if (KT > 1) load_slab(1, 1);
    cp_commit();

    const int g  = lane >> 3;
    const int li = lane & 7;

    unsigned af[2][4][4], bq[2][4][4];

    auto load_frags = [&](unsigned sA_u, unsigned sB_u, int ks, int buf){
        #pragma unroll
        for (int mt = 0; mt < 4; mt++){
            int row = m_off + mt*16 + li + (g & 1)*8;
            int ch  = ks*2 + (g >> 1);
            ldm_x4(af[buf][mt], sA_u + row*128 + ((ch ^ (row & 7))<<4));
        }
        #pragma unroll
        for (int np = 0; np < 4; np++){
            int row = n_off + np*16 + li + (g >> 1)*8;
            int ch  = ks*2 + (g & 1);
            ldm_x4(bq[buf][np], sB_u + row*128 + ((ch ^ (row & 7))<<4));
        }
    };

    for (int kt = 0; kt < KT; kt++){
        cp_wait<1>();
        __syncthreads();
        int kf = kt + 2;
        if (kf < KT) load_slab(kf % GSTAGES, kf);
        cp_commit();

        const unsigned sA_u = smem_u + (kt % GSTAGES)*STB;
        const unsigned sB_u = sA_u + SAB;

        load_frags(sA_u, sB_u, 0, 0);
        #pragma unroll
        for (int ks = 0; ks < 4; ks++){
            const int cur = ks & 1;
            if (ks < 3) load_frags(sA_u, sB_u, ks + 1, cur ^ 1);
            #pragma unroll
            for (int mt = 0; mt < 4; mt++)
                #pragma unroll
                for (int np = 0; np < 4; np++){
                    mma16(acc[mt][np*2+0], af[cur][mt], &bq[cur][np][0]);
                    mma16(acc[mt][np*2+1], af[cur][mt], &bq[cur][np][2]);
                }
        }
    }

    // ---- epilogue: stage C tile in smem, then coalesced uint4 stores ----
    cp_wait<0>();
    __syncthreads();
    __half* ctile = (__half*)smem;   // [BM][LDC_S]
    const int lr = lane >> 2, lc = lane & 3;

    #pragma unroll
    for (int mt = 0; mt < 4; mt++){
        #pragma unroll
        for (int nt = 0; nt < 8; nt++){
            int cl = n_off + nt*8 + lc*2;
            int cg = pn*BN + cl;
            #pragma unroll
            for (int half_ = 0; half_ < 2; half_++){
                int rl = m_off + mt*16 + lr + half_*8;
                float v0 = acc[mt][nt][half_*2+0];
                float v1 = acc[mt][nt][half_*2+1];
                __half2 hv;
                if constexpr (EPI == 1){
                    v0 += bias[cg]; v1 += bias[cg+1];
                    if (pn >= QKV3/BN)
                        hv = __floats2half2_rn(gelu_tanh(v0), gelu_tanh(v1));
                    else
                        hv = __floats2half2_rn(v0, v1);
                } else {
                    hv = __floats2half2_rn(v0, v1);
                }
                *(__half2*)&ctile[rl*LDC_S + cl] = hv;
            }
        }
    }
    __syncthreads();

    __half* dstbase;
    size_t stride;
    if constexpr (EPI == 1){
        if (pn >= QKV3/BN){ dstbase = (__half*)Cv2 + HID + (pn*BN - QKV3); stride = K2; }
        else              { dstbase = (__half*)Cv  + pn*BN;               stride = QKV3; }
    } else {
        dstbase = (__half*)Cv + (size_t)sk*NTOK*HID + pn*BN;
        stride = HID;
    }
    const int row0 = pm*BM;
    #pragma unroll
    for (int j = 0; j < 16; j++){
        int idx = j*128 + tid;
        int rl = idx >> 4;
        int q  = idx & 15;
        *(uint4*)&dstbase[(size_t)(row0+rl)*stride + q*8] =
            *(const uint4*)&ctile[rl*LDC_S + q*8];
    }
}

// ---------------- kernel: split-K reduce + bias + residual + gate ----------------
__global__ void __launch_bounds__(256, 8)
reduce_out(const __half* __restrict__ part,
           const float* __restrict__ x,
           const float* __restrict__ bias,
           const float* __restrict__ mod,
           float* __restrict__ out){
    size_t idx = (size_t)blockIdx.x*256 + threadIdx.x;
    int r = (int)(idx / (HID/4));
    int c = (int)(idx % (HID/4)) * 4;
    const float* gate = mod + (r >> 11)*MOD3 + 2*HID;
    float s0, s1, s2, s3;
    {
        float4 bv = *(const float4*)&bias[c];
        s0 = bv.x; s1 = bv.y; s2 = bv.z; s3 = bv.w;
    }
    #pragma unroll
    for (int p = 0; p < SPLITK; p++){
        uint2 u = *(const uint2*)&part[(size_t)p*NTOK*HID + (size_t)r*HID + c];
        __half2 h0 = *(__half2*)&u.x, h1 = *(__half2*)&u.y;
        float2 f0 = __half22float2(h0), f1 = __half22float2(h1);
        s0 += f0.x; s1 += f0.y; s2 += f1.x; s3 += f1.y;
    }
    float4 g4 = *(const float4*)&gate[c];
    float4 xv = *(const float4*)&x[(size_t)r*HID + c];
    float4 o;
    o.x = xv.x + g4.x*s0;
    o.y = xv.y + g4.y*s1;
    o.z = xv.z + g4.z*s2;
    o.w = xv.w + g4.w*s3;
    *(float4*)&out[(size_t)r*HID + c] = o;
}

// ---------------- kernel 4: per-token head-attention -> A2[:, :3072] ----------------
#define SKS 132
__global__ void __launch_bounds__(256, 4)
attn_kernel(const __half* __restrict__ h,
            const float* __restrict__ pe,
            const float* __restrict__ qsc,
            const float* __restrict__ ksc,
            __half* __restrict__ a2){
    __shared__ float sq[NH*HD], sk[NH*SKS], sv[NH*HD], ss[NH*NH];
    const int t = blockIdx.x;
    const int b = t >> 11;
    const int l = t & 2047;
    const int tid = threadIdx.x;
    const int lane = tid & 31;
    const int w = tid >> 5;

    const __half* hrow = h + (size_t)t*QKV3;

    for (int j = tid; j < 2304; j += 256){
        uint2 u = ((const uint2*)hrow)[j];
        __half2 p0 = *(__half2*)&u.x, p1 = *(__half2*)&u.y;
        float2 f0 = __half22float2(p0), f1 = __half22float2(p1);
        float4 v4; v4.x = f0.x; v4.y = f0.y; v4.z = f1.x; v4.w = f1.y;
        if (j < 768){
            ((float4*)sq)[j] = v4;
        } else if (j < 1536){
            int o = j - 768;
            *(float4*)&sk[(o >> 5)*SKS + (o & 31)*4] = v4;
        } else {
            ((float4*)sv)[j - 1536] = v4;
        }
    }
    __syncthreads();

    const float* pet = pe + ((size_t)(b*LL + l))*(HD/2)*4;
    float4 qs4 = *(const float4*)&qsc[lane*4];
    float4 ks4 = *(const float4*)&ksc[lane*4];
    float4 e0 = *(const float4*)&pet[lane*8];
    float4 e1 = *(const float4*)&pet[lane*8 + 4];

    #pragma unroll
    for (int i = 0; i < 3; i++){
        int hh = w + 8*i;
        float4 q4 = *(float4*)&sq[hh*HD + lane*4];
        float4 k4 = *(float4*)&sk[hh*SKS + lane*4];
        float pq = q4.x*q4.x + q4.y*q4.y + q4.z*q4.z + q4.w*q4.w;
        float pk = k4.x*k4.x + k4.y*k4.y + k4.z*k4.z + k4.w*k4.w;
        #pragma unroll
        for (int o = 16; o > 0; o >>= 1){
            pq += __shfl_xor_sync(0xffffffffu, pq, o);
            pk += __shfl_xor_sync(0xffffffffu, pk, o);
        }
        float rq = rsqrtf(pq*(1.0f/HD) + 1e-6f);
        float rk = rsqrtf(pk*(1.0f/HD) + 1e-6f);
        q4.x *= rq*qs4.x; q4.y *= rq*qs4.y; q4.z *= rq*qs4.z; q4.w *= rq*qs4.w;
        k4.x *= rk*ks4.x; k4.y *= rk*ks4.y; k4.z *= rk*ks4.z; k4.w *= rk*ks4.w;
        float4 qo, ko;
        qo.x = e0.x*q4.x + e0.y*q4.y;  qo.y = e0.z*q4.x + e0.w*q4.y;
        qo.z = e1.x*q4.z + e1.y*q4.w;  qo.w = e1.z*q4.z + e1.w*q4.w;
        ko.x = e0.x*k4.x + e0.y*k4.y;  ko.y = e0.z*k4.x + e0.w*k4.y;
        ko.z = e1.x*k4.z + e1.y*k4.w;  ko.w = e1.z*k4.z + e1.w*k4.w;
        const float sc = 0.08838834764831845f; // 1/sqrt(128)
        qo.x *= sc; qo.y *= sc; qo.z *= sc; qo.w *= sc;
        *(float4*)&sq[hh*HD + lane*4] = qo;
        *(float4*)&sk[hh*SKS + lane*4] = ko;
    }
    __syncthreads();

    const int g24 = (lane < NH) ? lane : 0;
    #pragma unroll
    for (int i = 0; i < 3; i++){
        int hh = w + 8*i;
        float s = 0.f;
        const float* qrow = &sq[hh*HD];
        const float* krow = &sk[g24*SKS];
        #pragma unroll 8
        for (int d4 = 0; d4 < 32; d4++){
            float4 qv = *(const float4*)&qrow[d4*4];
            float4 kv = *(const float4*)&krow[d4*4];
            s += qv.x*kv.x + qv.y*kv.y + qv.z*kv.z + qv.w*kv.w;
        }
        float v = (lane < NH) ? s : -1e30f;
        float mx = v;
        #pragma unroll
        for (int o = 16; o > 0; o >>= 1) mx = fmaxf(mx, __shfl_xor_sync(0xffffffffu, mx, o));
        float e = (lane < NH) ? expf(v - mx) : 0.f;
        float sum = e;
        #pragma unroll
        for (int o = 16; o > 0; o >>= 1) sum += __shfl_xor_sync(0xffffffffu, sum, o);
        if (lane < NH) ss[hh*NH + lane] = e / sum;
    }
    __syncwarp();

    #pragma unroll
    for (int i = 0; i < 3; i++){
        int hh = w + 8*i;
        float4 accv; accv.x = accv.y = accv.z = accv.w = 0.f;
        #pragma unroll 8
        for (int gg = 0; gg < NH; gg++){
            float p = ss[hh*NH + gg];
            float4 vv = *(const float4*)&sv[gg*HD + lane*4];
            accv.x += p*vv.x; accv.y += p*vv.y; accv.z += p*vv.z; accv.w += p*vv.w;
        }
        __half2 p0 = __floats2half2_rn(accv.x, accv.y);
        __half2 p1 = __floats2half2_rn(accv.z, accv.w);
        uint2 u; u.x = *(unsigned*)&p0; u.y = *(unsigned*)&p1;
        *(uint2*)&a2[(size_t)t*K2 + hh*HD + lane*4] = u;
    }
}

// ---------------- launch ----------------
extern "C" void kernel_launch(void* const* d_in, const int* in_sizes, int n_in,
                              void* d_out, int out_size){
    const float* x      = (const float*)d_in[0];
    const float* vec    = (const float*)d_in[1];
    const float* pe     = (const float*)d_in[2];
    const float* mod_w  = (const float*)d_in[3];
    const float* mod_b  = (const float*)d_in[4];
    const float* lin1_w = (const float*)d_in[5];
    const float* lin1_b = (const float*)d_in[6];
    const float* lin2_w = (const float*)d_in[7];
    const float* lin2_b = (const float*)d_in[8];
    const float* q_scale= (const float*)d_in[9];
    const float* k_scale= (const float*)d_in[10];
    float* out = (float*)d_out;

    float *d_mod;
    __half *d_xh, *d_h, *d_a2h, *d_w1t, *d_w2t, *d_part;
    cudaGetSymbolAddress((void**)&d_mod,  g_mod);
    cudaGetSymbolAddress((void**)&d_xh,   g_xh);
    cudaGetSymbolAddress((void**)&d_h,    g_h);
    cudaGetSymbolAddress((void**)&d_a2h,  g_a2h);
    cudaGetSymbolAddress((void**)&d_w1t,  g_w1t);
    cudaGetSymbolAddress((void**)&d_w2t,  g_w2t);
    cudaGetSymbolAddress((void**)&d_part, g_part);

    cudaFuncSetAttribute(gemm_f16<1>, cudaFuncAttributeMaxDynamicSharedMemorySize, GEMM_SMEM);
    cudaFuncSetAttribute(gemm_f16<2>, cudaFuncAttributeMaxDynamicSharedMemorySize, GEMM_SMEM);

    // fork transposes onto side stream; overlap ONLY with mod+ln, join before GEMM1
    cudaStream_t s1;
    cudaStreamCreateWithFlags(&s1, cudaStreamNonBlocking);
    cudaEvent_t evFork, evT;
    cudaEventCreateWithFlags(&evFork, cudaEventDisableTiming);
    cudaEventCreateWithFlags(&evT,    cudaEventDisableTiming);

    cudaEventRecord(evFork, 0);
    cudaStreamWaitEvent(s1, evFork, 0);
    transpose_half<<<dim3(N1/64, HID/64), 256, 0, s1>>>(lin1_w, d_w1t, HID, N1);
    transpose_half<<<dim3(HID/64, K2/64), 256, 0, s1>>>(lin2_w, d_w2t, K2, HID);
    cudaEventRecord(evT, s1);

    // main stream: mod -> ln (latency-bound, tolerate co-residency)
    mod_kernel<<<dim3(MOD3/64, BB), 256>>>(vec, mod_w, mod_b, d_mod);
    ln_mod_kernel<<<NTOK, 256>>>(x, d_mod, d_xh);

    // join BOTH transposes before any GEMM
    cudaStreamWaitEvent(0, evT, 0);

    // 3) h = x_mod @ lin1_w + lin1_b ; qkv -> g_h, gelu(mlp) -> g_a2h
    gemm_f16<1><<<(NTOK/BM)*(N1/BN), 128, GEMM_SMEM>>>(
        d_xh, HID, d_w1t, HID, lin1_b, d_h, NTOK, N1, HID, d_a2h);

    // 4) per-token attention -> A2[:, :3072]
    attn_kernel<<<NTOK, 256>>>(d_h, pe, q_scale, k_scale, d_a2h);

    // 5a) split-K partials: A2 @ lin2_w  (SPLITK=5 → 3840 CTAs ≈ 12.97 waves)
    gemm_f16<2><<<(NTOK/BM)*(HID/BN)*SPLITK, 128, GEMM_SMEM>>>(
        d_a2h, K2, d_w2t, K2, nullptr, d_part, NTOK, HID, KSPL, nullptr);

    // 5b) out = x + gate*(sum partials + bias)
    reduce_out<<<(NTOK*HID/4)/256, 256>>>(d_part, x, lin2_b, d_mod, out);
}